// round 13
// baseline (speedup 1.0000x reference)
#include <cuda_runtime.h>
#include <cuda_bf16.h>
#include <cstdint>

// ---------------------------------------------------------------------------
// Problem constants
// ---------------------------------------------------------------------------
constexpr int CCH   = 66;
constexpr int TLEN  = 96;
constexpr int BSZ   = 2048;
constexpr int FIN   = 9 * CCH * 12;   // 7128
constexpr int HID   = 1936;
constexpr int NCLS  = 14;

// fc1 GEMM padded dims (split bf16: A'=[Ahi|Ahi|Alo], B'=[Bhi|Blo|Bhi])
constexpr int KSEC  = 7168;
constexpr int KP    = 3 * KSEC;       // 21504
constexpr int NPAD  = 2048;
constexpr int KT    = KP / 32;        // 672

// ---------------------------------------------------------------------------
// Scratch
// ---------------------------------------------------------------------------
__device__ __align__(16) float g_xt[(size_t)BSZ * CCH * TLEN];
__device__ __align__(16) float g_feat[(size_t)BSZ * FIN];
__device__ __align__(16) float g_h[(size_t)BSZ * HID];
__device__ __align__(16) __nv_bfloat16 g_A2[(size_t)BSZ * KP];
__device__ __align__(16) __nv_bfloat16 g_B2[(size_t)NPAD * KP];

// ---------------------------------------------------------------------------
// PTX helpers (sm_80+ portable)
// ---------------------------------------------------------------------------
__device__ __forceinline__ uint32_t smem_to_u32(const void* p) {
    uint32_t a;
    asm("{ .reg .u64 t; cvta.to.shared.u64 t, %1; cvt.u32.u64 %0, t; }" : "=r"(a) : "l"(p));
    return a;
}
__device__ __forceinline__ void cp16(uint32_t dst, const void* src) {
    asm volatile("cp.async.cg.shared.global [%0], [%1], 16;" :: "r"(dst), "l"(src));
}
#define CP_COMMIT() asm volatile("cp.async.commit_group;" ::: "memory")
#define CP_WAIT2()  asm volatile("cp.async.wait_group 2;" ::: "memory")

__device__ __forceinline__ void ldsm_x4(uint32_t* r, uint32_t addr) {
    asm volatile("ldmatrix.sync.aligned.m8n8.x4.shared.b16 {%0,%1,%2,%3}, [%4];"
                 : "=r"(r[0]), "=r"(r[1]), "=r"(r[2]), "=r"(r[3]) : "r"(addr));
}
__device__ __forceinline__ void mma16816(float* d, const uint32_t* a,
                                         uint32_t b0, uint32_t b1) {
    asm volatile(
        "mma.sync.aligned.m16n8k16.row.col.f32.bf16.bf16.f32 "
        "{%0,%1,%2,%3}, {%4,%5,%6,%7}, {%8,%9}, {%0,%1,%2,%3};"
        : "+f"(d[0]), "+f"(d[1]), "+f"(d[2]), "+f"(d[3])
        : "r"(a[0]), "r"(a[1]), "r"(a[2]), "r"(a[3]), "r"(b0), "r"(b1));
}

// ---------------------------------------------------------------------------
// Transpose: x (B, T, C) -> g_xt (B, C, T)
// ---------------------------------------------------------------------------
__global__ void __launch_bounds__(256) transpose_kernel(const float* __restrict__ x) {
    __shared__ float s[TLEN * CCH];
    const int b = blockIdx.x;
    const float* src = x + (size_t)b * TLEN * CCH;
    for (int i = threadIdx.x; i < TLEN * CCH; i += 256) s[i] = src[i];
    __syncthreads();
    float* dst = g_xt + (size_t)b * CCH * TLEN;
    for (int i = threadIdx.x; i < TLEN * CCH; i += 256) {
        int c = i / TLEN, t = i - c * TLEN;
        dst[i] = s[t * CCH + c];
    }
}

// ---------------------------------------------------------------------------
// Feature extraction: warp-per-(b,c). 256-thread block = 8 warps = 8 batches
// of the SAME channel. Weights staged once per block; only __syncwarp()
// inside the per-warp pipeline.
// ---------------------------------------------------------------------------
template<int K, int PAD>
__device__ __forceinline__ void run_branch_w(
    const float* xsp, float* hs, float* z1,
    const float* ws,  const float* bs,
    const float* wi1, const float* bi1,
    const float* wi2, const float* bi2,
    float* fo, int slot_base, int lane)
{
    {   // stage 1: shared conv 1->8 (96), relu, pool2 -> hs rows of 48
        const int o = lane >> 2, g = lane & 3;      // o 0..7, g 0..3
        float wreg[K];
        #pragma unroll
        for (int k = 0; k < K; k++) wreg[k] = ws[o * K + k];
        const float bo = bs[o];
        float* hrow = hs + o * 56 + 4;
        #pragma unroll
        for (int it = 0; it < 12; it++) {
            const int uu = g + it * 4;              // 0..47
            const int t0 = 2 * uu - PAD;
            float v[K + 1];
            #pragma unroll
            for (int j = 0; j <= K; j++) v[j] = xsp[t0 + j];
            float a0 = bo, a1 = bo;
            #pragma unroll
            for (int k = 0; k < K; k++) {
                a0 = fmaf(v[k],     wreg[k], a0);
                a1 = fmaf(v[k + 1], wreg[k], a1);
            }
            hrow[uu] = 0.5f * (fmaxf(a0, 0.f) + fmaxf(a1, 0.f));
        }
    }
    __syncwarp();
    {   // stage 2: grouped conv 8->4 (48), relu, pool2 -> z1 rows of 24
        const int j = lane >> 3, g = lane & 7;      // j 0..3, g 0..7
        const float bj = bi1[j];
        const float* wbase = wi1 + j * 8 * K;
        #pragma unroll
        for (int it = 0; it < 3; it++) {
            const int uu = g + it * 8;              // 0..23
            const int t0 = 2 * uu - PAD;
            float a0 = bj, a1 = bj;
            #pragma unroll
            for (int i = 0; i < 8; i++) {
                const float* hrow = hs + i * 56 + 4 + t0;
                const float* wr = wbase + i * K;
                float v[K + 1];
                #pragma unroll
                for (int jj = 0; jj <= K; jj++) v[jj] = hrow[jj];
                #pragma unroll
                for (int k = 0; k < K; k++) {
                    float w = wr[k];
                    a0 = fmaf(v[k],     w, a0);
                    a1 = fmaf(v[k + 1], w, a1);
                }
            }
            z1[j * 32 + 4 + uu] = 0.5f * (fmaxf(a0, 0.f) + fmaxf(a1, 0.f));
        }
    }
    __syncwarp();
    {   // stage 3: grouped conv 4->4 (24), relu, pool2 -> 12 outputs
        const int j = lane >> 3, g = lane & 7;
        for (int uu = g; uu < 12; uu += 8) {
            const int t0 = 2 * uu - PAD;
            float a0 = bi2[j], a1 = bi2[j];
            #pragma unroll
            for (int i = 0; i < 4; i++) {
                const float* zrow = z1 + i * 32 + 4 + t0;
                const float* wr = wi2 + (j * 4 + i) * K;
                float v[K + 1];
                #pragma unroll
                for (int jj = 0; jj <= K; jj++) v[jj] = zrow[jj];
                #pragma unroll
                for (int k = 0; k < K; k++) {
                    float w = wr[k];
                    a0 = fmaf(v[k],     w, a0);
                    a1 = fmaf(v[k + 1], w, a1);
                }
            }
            fo[(slot_base + j) * 12 + uu] = 0.5f * (fmaxf(a0, 0.f) + fmaxf(a1, 0.f));
        }
    }
    __syncwarp();   // protect hs/z1 reuse by the next branch
}

__global__ void __launch_bounds__(256) feat_kernel(
    const float* __restrict__ w_hs, const float* __restrict__ b_hs,
    const float* __restrict__ w_ls, const float* __restrict__ b_ls,
    const float* __restrict__ w_hi1, const float* __restrict__ b_hi1,
    const float* __restrict__ w_hi2, const float* __restrict__ b_hi2,
    const float* __restrict__ w_li1, const float* __restrict__ b_li1,
    const float* __restrict__ w_li2, const float* __restrict__ b_li2)
{
    const int c    = blockIdx.x;
    const int tid  = threadIdx.x;
    const int w    = tid >> 5;         // warp 0..7 -> batch
    const int lane = tid & 31;
    const int b    = blockIdx.y * 8 + w;

    __shared__ float xs[8][104];
    __shared__ float hs[8][8 * 56];
    __shared__ float z1[8][4 * 32];
    __shared__ float sw_h[8 * 7],       sw_l[8 * 3];
    __shared__ float swi1_h[4 * 8 * 7], swi2_h[4 * 4 * 7];
    __shared__ float swi1_l[4 * 8 * 3], swi2_l[4 * 4 * 3];
    __shared__ float sb_h[8], sb_l[8];
    __shared__ float sbi1_h[4], sbi2_h[4], sbi1_l[4], sbi2_l[4];

    // per-warp halo zeroing + x stage-in (warp-local data)
    for (int i = lane; i < 8 * 56; i += 32) hs[w][i] = 0.f;
    for (int i = lane; i < 4 * 32; i += 32) z1[w][i] = 0.f;
    if (lane < 4) { xs[w][lane] = 0.f; xs[w][100 + lane] = 0.f; }
    const float* xrow = g_xt + ((size_t)b * CCH + c) * TLEN;
    for (int i = lane; i < 96; i += 32) xs[w][4 + i] = xrow[i];

    // weights staged once per block (shared by all 8 warps; same channel)
    if (tid < 56)  sw_h[tid] = w_hs[tid];
    if (tid >= 64 && tid < 88)   sw_l[tid - 64]  = w_ls[tid - 64];
    if (tid >= 96 && tid < 104)  sb_h[tid - 96]  = b_hs[tid - 96];
    if (tid >= 104 && tid < 112) sb_l[tid - 104] = b_ls[tid - 104];
    if (tid >= 128 && tid < 224) swi1_l[tid - 128] = w_li1[c * 96 + (tid - 128)];
    if (tid < 224) swi1_h[tid] = w_hi1[c * 224 + tid];
    if (tid < 112) swi2_h[tid] = w_hi2[c * 112 + tid];
    if (tid >= 224 && tid < 256) {
        const int i = tid - 224;
        swi2_l[i]      = w_li2[c * 48 + i];
        swi2_l[i + 16] = w_li2[c * 48 + i + 16];   // last 16 covered below
    }
    if (tid >= 112 && tid < 128) swi2_l[32 + (tid - 112)] = w_li2[c * 48 + 32 + (tid - 112)];
    if (tid >= 88 && tid < 92)  sbi1_h[tid - 88] = b_hi1[c * 4 + (tid - 88)];
    if (tid >= 92 && tid < 96)  sbi2_h[tid - 92] = b_hi2[c * 4 + (tid - 92)];
    if (tid >= 60 && tid < 64)  sbi1_l[tid - 60] = b_li1[c * 4 + (tid - 60)];
    if (tid >= 56 && tid < 60)  sbi2_l[tid - 56] = b_li2[c * 4 + (tid - 56)];
    __syncthreads();   // single block barrier: weights + halos visible

    float* fo = g_feat + (size_t)b * FIN + c * 108;
    const float* xsp = xs[w] + 4;

    if (lane < 12) {   // slot 0: mean of 8
        float s = 0.f;
        #pragma unroll
        for (int k = 0; k < 8; k++) s += xsp[lane * 8 + k];
        fo[lane] = s * 0.125f;
    }

    run_branch_w<3, 1>(xsp, hs[w], z1[w], sw_l, sb_l, swi1_l, sbi1_l,
                       swi2_l, sbi2_l, fo, 1, lane);
    run_branch_w<7, 3>(xsp, hs[w], z1[w], sw_h, sb_h, swi1_h, sbi1_h,
                       swi2_h, sbi2_h, fo, 5, lane);
}

// ---------------------------------------------------------------------------
// Split-precision conversions
// ---------------------------------------------------------------------------
__device__ __forceinline__ void split8(const float* v, __nv_bfloat16* hi, __nv_bfloat16* lo) {
    #pragma unroll
    for (int i = 0; i < 8; i++) {
        __nv_bfloat16 h = __float2bfloat16(v[i]);
        hi[i] = h;
        lo[i] = __float2bfloat16(v[i] - __bfloat162float(h));
    }
}

__global__ void __launch_bounds__(256) convA_kernel() {
    const size_t idx = (size_t)blockIdx.x * 256 + threadIdx.x;   // 2048*896
    const int m  = (int)(idx / 896);
    const int kb = (int)(idx % 896);
    const int k0 = kb * 8;
    float v[8];
    if (kb < 891) {
        float4 a = *(const float4*)(g_feat + (size_t)m * FIN + k0);
        float4 b = *(const float4*)(g_feat + (size_t)m * FIN + k0 + 4);
        v[0]=a.x; v[1]=a.y; v[2]=a.z; v[3]=a.w; v[4]=b.x; v[5]=b.y; v[6]=b.z; v[7]=b.w;
    } else {
        #pragma unroll
        for (int i = 0; i < 8; i++) v[i] = 0.f;
    }
    __align__(16) __nv_bfloat16 hi[8], lo[8];
    split8(v, hi, lo);
    __nv_bfloat16* dst = g_A2 + (size_t)m * KP + k0;
    *(uint4*)(dst)            = *(uint4*)hi;
    *(uint4*)(dst + KSEC)     = *(uint4*)hi;
    *(uint4*)(dst + 2 * KSEC) = *(uint4*)lo;
}

__global__ void __launch_bounds__(256) convB_kernel(const float* __restrict__ w1) {
    const size_t idx = (size_t)blockIdx.x * 256 + threadIdx.x;   // 2048*896
    const int n  = (int)(idx / 896);
    const int kb = (int)(idx % 896);
    const int k0 = kb * 8;
    float v[8];
    if (n < HID && kb < 891) {
        float4 a = *(const float4*)(w1 + (size_t)n * FIN + k0);
        float4 b = *(const float4*)(w1 + (size_t)n * FIN + k0 + 4);
        v[0]=a.x; v[1]=a.y; v[2]=a.z; v[3]=a.w; v[4]=b.x; v[5]=b.y; v[6]=b.z; v[7]=b.w;
    } else {
        #pragma unroll
        for (int i = 0; i < 8; i++) v[i] = 0.f;
    }
    __align__(16) __nv_bfloat16 hi[8], lo[8];
    split8(v, hi, lo);
    __nv_bfloat16* dst = g_B2 + (size_t)n * KP + k0;
    *(uint4*)(dst)            = *(uint4*)hi;
    *(uint4*)(dst + KSEC)     = *(uint4*)lo;
    *(uint4*)(dst + 2 * KSEC) = *(uint4*)hi;
}

// ---------------------------------------------------------------------------
// fc1 GEMM (HMMA bf16) — R4-exact config (best measured):
// 128x128x32 tile, 256 threads / 8 warps (2m x 4n), warp tile 64x32,
// 4-stage cp.async (64KB). grid 16x16 = 256 blocks. NO min-blocks clause.
// ---------------------------------------------------------------------------
constexpr int GSTAGES = 4;
constexpr int STAGE_BYTES = 16384;
constexpr int GSMEM_BYTES = GSTAGES * STAGE_BYTES;   // 64 KB

__global__ void __launch_bounds__(256) gemm_kernel(const float* __restrict__ bias) {
    extern __shared__ char smem[];
    const uint32_t smem_u32 = smem_to_u32(smem);
    const int tid  = threadIdx.x;
    const int wid  = tid >> 5;
    const int lane = tid & 31;
    const int bm = blockIdx.y * 128;
    const int bn = blockIdx.x * 128;

    const int warp_m = wid & 1;          // 2 -> 64 rows each
    const int warp_n = wid >> 1;         // 4 -> 32 cols each

    const int lcu  = tid & 3;
    const int lrow = tid >> 2;           // 0..63 ; rows lrow, lrow+64
    const __nv_bfloat16* srcA[2];
    const __nv_bfloat16* srcB[2];
    uint32_t dstA[2], dstB[2];
    #pragma unroll
    for (int i = 0; i < 2; i++) {
        const int r = lrow + 64 * i;
        srcA[i] = g_A2 + (size_t)(bm + r) * KP + lcu * 8;
        srcB[i] = g_B2 + (size_t)(bn + r) * KP + lcu * 8;
        const uint32_t sw = (uint32_t)((lcu ^ ((r >> 1) & 3)) << 4);
        dstA[i] = r * 64 + sw;
        dstB[i] = 8192 + r * 64 + sw;
    }

    const int g8 = lane >> 3;
    const int l8 = lane & 7;
    uint32_t aoff[8];
    #pragma unroll
    for (int mt = 0; mt < 4; mt++) {
        const int mrow = warp_m * 64 + mt * 16 + (g8 & 1) * 8 + l8;
        const int s = (mrow >> 1) & 3;
        #pragma unroll
        for (int ks = 0; ks < 2; ks++) {
            const int cu = 2 * ks + (g8 >> 1);
            aoff[mt * 2 + ks] = mrow * 64 + ((cu ^ s) << 4);
        }
    }
    uint32_t boff[4];
    #pragma unroll
    for (int p = 0; p < 2; p++) {
        const int nrow = warp_n * 32 + p * 16 + (g8 >> 1) * 8 + l8;
        const int s = (nrow >> 1) & 3;
        #pragma unroll
        for (int ks = 0; ks < 2; ks++) {
            const int cu = 2 * ks + (g8 & 1);
            boff[p * 2 + ks] = 8192 + nrow * 64 + ((cu ^ s) << 4);
        }
    }

    float acc[4][4][4];
    #pragma unroll
    for (int mt = 0; mt < 4; mt++)
        #pragma unroll
        for (int nt = 0; nt < 4; nt++)
            #pragma unroll
            for (int e = 0; e < 4; e++) acc[mt][nt][e] = 0.f;

    #pragma unroll
    for (int kt = 0; kt < GSTAGES - 1; kt++) {
        const uint32_t sb = smem_u32 + kt * STAGE_BYTES;
        #pragma unroll
        for (int i = 0; i < 2; i++) {
            cp16(sb + dstA[i], srcA[i] + (size_t)kt * 32);
            cp16(sb + dstB[i], srcB[i] + (size_t)kt * 32);
        }
        CP_COMMIT();
    }

    for (int kt = 0; kt < KT; kt++) {
        CP_WAIT2();
        __syncthreads();

        const int knext = kt + GSTAGES - 1;
        if (knext < KT) {
            const uint32_t sb = smem_u32 + (knext & 3) * STAGE_BYTES;
            #pragma unroll
            for (int i = 0; i < 2; i++) {
                cp16(sb + dstA[i], srcA[i] + (size_t)knext * 32);
                cp16(sb + dstB[i], srcB[i] + (size_t)knext * 32);
            }
        }
        CP_COMMIT();

        const uint32_t sb = smem_u32 + (kt & 3) * STAGE_BYTES;
        #pragma unroll
        for (int ks = 0; ks < 2; ks++) {
            uint32_t afr[4][4], bfr[2][4];
            #pragma unroll
            for (int mt = 0; mt < 4; mt++) ldsm_x4(afr[mt], sb + aoff[mt * 2 + ks]);
            #pragma unroll
            for (int p = 0; p < 2; p++)    ldsm_x4(bfr[p],  sb + boff[p * 2 + ks]);
            #pragma unroll
            for (int mt = 0; mt < 4; mt++)
                #pragma unroll
                for (int nt = 0; nt < 4; nt++)
                    mma16816(acc[mt][nt], afr[mt],
                             bfr[nt >> 1][(nt & 1) * 2],
                             bfr[nt >> 1][(nt & 1) * 2 + 1]);
        }
    }

    const int qrow = lane >> 2;
    const int qcol = (lane & 3) * 2;
    #pragma unroll
    for (int mt = 0; mt < 4; mt++) {
        #pragma unroll
        for (int nt = 0; nt < 4; nt++) {
            const int n = bn + warp_n * 32 + nt * 8 + qcol;
            if (n >= HID) continue;
            const float b0 = bias[n], b1 = bias[n + 1];
            #pragma unroll
            for (int half = 0; half < 2; half++) {
                const int m = bm + warp_m * 64 + mt * 16 + qrow + half * 8;
                float* o = g_h + (size_t)m * HID + n;
                o[0] = fmaxf(acc[mt][nt][half * 2 + 0] + b0, 0.f);
                o[1] = fmaxf(acc[mt][nt][half * 2 + 1] + b1, 0.f);
            }
        }
    }
}

// ---------------------------------------------------------------------------
// fc2: warp-per-row, 14 outputs in registers, g_h read exactly once.
// ---------------------------------------------------------------------------
__global__ void __launch_bounds__(256) fc2_kernel(
    const float* __restrict__ w2, const float* __restrict__ b2,
    float* __restrict__ out)
{
    const int wid  = threadIdx.x >> 5;
    const int lane = threadIdx.x & 31;
    const int m = blockIdx.x * 8 + wid;

    const float* hrow = g_h + (size_t)m * HID;
    float acc[NCLS];
    #pragma unroll
    for (int n = 0; n < NCLS; n++) acc[n] = 0.f;

    for (int k = lane; k < HID; k += 32) {
        const float h = hrow[k];
        #pragma unroll
        for (int n = 0; n < NCLS; n++)
            acc[n] = fmaf(h, w2[n * HID + k], acc[n]);
    }
    #pragma unroll
    for (int n = 0; n < NCLS; n++)
        #pragma unroll
        for (int off = 16; off > 0; off >>= 1)
            acc[n] += __shfl_down_sync(0xffffffffu, acc[n], off);
    if (lane == 0) {
        #pragma unroll
        for (int n = 0; n < NCLS; n++)
            out[m * NCLS + n] = acc[n] + b2[n];
    }
}

// ---------------------------------------------------------------------------
// Entry
// ---------------------------------------------------------------------------
extern "C" void kernel_launch(void* const* d_in, const int* in_sizes, int n_in,
                              void* d_out, int out_size)
{
    const float* x     = (const float*)d_in[0];
    const float* w_hs  = (const float*)d_in[1];
    const float* b_hs  = (const float*)d_in[2];
    const float* w_ls  = (const float*)d_in[3];
    const float* b_ls  = (const float*)d_in[4];
    const float* w_hi1 = (const float*)d_in[5];
    const float* b_hi1 = (const float*)d_in[6];
    const float* w_hi2 = (const float*)d_in[7];
    const float* b_hi2 = (const float*)d_in[8];
    const float* w_li1 = (const float*)d_in[9];
    const float* b_li1 = (const float*)d_in[10];
    const float* w_li2 = (const float*)d_in[11];
    const float* b_li2 = (const float*)d_in[12];
    const float* w_fc1 = (const float*)d_in[13];
    const float* b_fc1 = (const float*)d_in[14];
    const float* w_fc2 = (const float*)d_in[15];
    const float* b_fc2 = (const float*)d_in[16];
    float* out = (float*)d_out;

    static bool attr_set = false;
    if (!attr_set) {
        cudaFuncSetAttribute(gemm_kernel, cudaFuncAttributeMaxDynamicSharedMemorySize,
                             GSMEM_BYTES);
        attr_set = true;
    }

    transpose_kernel<<<BSZ, 256>>>(x);
    convB_kernel<<<(NPAD * 896) / 256, 256>>>(w_fc1);
    feat_kernel<<<dim3(CCH, BSZ / 8), 256>>>(w_hs, b_hs, w_ls, b_ls,
                                             w_hi1, b_hi1, w_hi2, b_hi2,
                                             w_li1, b_li1, w_li2, b_li2);
    convA_kernel<<<(BSZ * 896) / 256, 256>>>();
    gemm_kernel<<<dim3(16, 16), 256, GSMEM_BYTES>>>(b_fc1);
    fc2_kernel<<<BSZ / 8, 256>>>(w_fc2, b_fc2, out);
}

// round 14
// speedup vs baseline: 1.3217x; 1.3217x over previous
#include <cuda_runtime.h>
#include <cuda_bf16.h>
#include <cstdint>

// ---------------------------------------------------------------------------
// Problem constants
// ---------------------------------------------------------------------------
constexpr int CCH   = 66;
constexpr int TLEN  = 96;
constexpr int BSZ   = 2048;
constexpr int FIN   = 9 * CCH * 12;   // 7128
constexpr int HID   = 1936;
constexpr int NCLS  = 14;

// fc1 GEMM padded dims (split bf16: A'=[Ahi|Ahi|Alo], B'=[Bhi|Blo|Bhi])
constexpr int KSEC  = 7168;
constexpr int KP    = 3 * KSEC;       // 21504
constexpr int NPAD  = 2048;
constexpr int KT    = KP / 32;        // 672

// ---------------------------------------------------------------------------
// Scratch
// ---------------------------------------------------------------------------
__device__ __align__(16) float g_xt[(size_t)BSZ * CCH * TLEN];
__device__ __align__(16) float g_feat[(size_t)BSZ * FIN];
__device__ __align__(16) float g_h[(size_t)BSZ * HID];
__device__ __align__(16) __nv_bfloat16 g_A2[(size_t)BSZ * KP];
__device__ __align__(16) __nv_bfloat16 g_B2[(size_t)NPAD * KP];

// ---------------------------------------------------------------------------
// PTX helpers (sm_80+ portable)
// ---------------------------------------------------------------------------
__device__ __forceinline__ uint32_t smem_to_u32(const void* p) {
    uint32_t a;
    asm("{ .reg .u64 t; cvta.to.shared.u64 t, %1; cvt.u32.u64 %0, t; }" : "=r"(a) : "l"(p));
    return a;
}
__device__ __forceinline__ void cp16(uint32_t dst, const void* src) {
    asm volatile("cp.async.cg.shared.global [%0], [%1], 16;" :: "r"(dst), "l"(src));
}
#define CP_COMMIT() asm volatile("cp.async.commit_group;" ::: "memory")
#define CP_WAIT2()  asm volatile("cp.async.wait_group 2;" ::: "memory")

__device__ __forceinline__ void ldsm_x4(uint32_t* r, uint32_t addr) {
    asm volatile("ldmatrix.sync.aligned.m8n8.x4.shared.b16 {%0,%1,%2,%3}, [%4];"
                 : "=r"(r[0]), "=r"(r[1]), "=r"(r[2]), "=r"(r[3]) : "r"(addr));
}
__device__ __forceinline__ void mma16816(float* d, const uint32_t* a,
                                         uint32_t b0, uint32_t b1) {
    asm volatile(
        "mma.sync.aligned.m16n8k16.row.col.f32.bf16.bf16.f32 "
        "{%0,%1,%2,%3}, {%4,%5,%6,%7}, {%8,%9}, {%0,%1,%2,%3};"
        : "+f"(d[0]), "+f"(d[1]), "+f"(d[2]), "+f"(d[3])
        : "r"(a[0]), "r"(a[1]), "r"(a[2]), "r"(a[3]), "r"(b0), "r"(b1));
}

// ---------------------------------------------------------------------------
// Transpose: x (B, T, C) -> g_xt (B, C, T)
// ---------------------------------------------------------------------------
__global__ void __launch_bounds__(256) transpose_kernel(const float* __restrict__ x) {
    __shared__ float s[TLEN * CCH];
    const int b = blockIdx.x;
    const float* src = x + (size_t)b * TLEN * CCH;
    for (int i = threadIdx.x; i < TLEN * CCH; i += 256) s[i] = src[i];
    __syncthreads();
    float* dst = g_xt + (size_t)b * CCH * TLEN;
    for (int i = threadIdx.x; i < TLEN * CCH; i += 256) {
        int c = i / TLEN, t = i - c * TLEN;
        dst[i] = s[t * CCH + c];
    }
}

// ---------------------------------------------------------------------------
// Feature extraction: one 64-thread block per (b, c). R4 structure exactly
// (padded halos, 2-output windows, fp32 out).
// ---------------------------------------------------------------------------
template<int K, int PAD>
__device__ __forceinline__ void run_branch(
    const float* xsp, float* hs, float* z1,
    const float* ws,  const float* bs,
    const float* wi1, const float* bi1,
    const float* wi2, const float* bi2,
    float* fo, int slot_base, int tid)
{
    {   // stage 1: shared conv 1->8 (96), relu, pool2 -> hs rows of 48
        const int o = tid >> 3, g = tid & 7;
        float wreg[K];
        #pragma unroll
        for (int k = 0; k < K; k++) wreg[k] = ws[o * K + k];
        const float bo = bs[o];
        float* hrow = hs + o * 56 + 4;
        #pragma unroll
        for (int ub = 0; ub < 48; ub += 8) {
            const int uu = ub + g;
            const int t0 = 2 * uu - PAD;
            float v[K + 1];
            #pragma unroll
            for (int j = 0; j <= K; j++) v[j] = xsp[t0 + j];
            float a0 = bo, a1 = bo;
            #pragma unroll
            for (int k = 0; k < K; k++) {
                a0 = fmaf(v[k],     wreg[k], a0);
                a1 = fmaf(v[k + 1], wreg[k], a1);
            }
            hrow[uu] = 0.5f * (fmaxf(a0, 0.f) + fmaxf(a1, 0.f));
        }
    }
    __syncthreads();
    {   // stage 2: grouped conv 8->4 (48), relu, pool2 -> z1 rows of 24
        const int j = tid >> 4, g = tid & 15;
        const float bj = bi1[j];
        const float* wbase = wi1 + j * 8 * K;
        for (int uu = g; uu < 24; uu += 16) {
            const int t0 = 2 * uu - PAD;
            float a0 = bj, a1 = bj;
            #pragma unroll
            for (int i = 0; i < 8; i++) {
                const float* hrow = hs + i * 56 + 4 + t0;
                const float* wr = wbase + i * K;
                float v[K + 1];
                #pragma unroll
                for (int jj = 0; jj <= K; jj++) v[jj] = hrow[jj];
                #pragma unroll
                for (int k = 0; k < K; k++) {
                    float w = wr[k];
                    a0 = fmaf(v[k],     w, a0);
                    a1 = fmaf(v[k + 1], w, a1);
                }
            }
            z1[j * 32 + 4 + uu] = 0.5f * (fmaxf(a0, 0.f) + fmaxf(a1, 0.f));
        }
    }
    __syncthreads();
    {   // stage 3: grouped conv 4->4 (24), relu, pool2 -> 12 outputs
        const int j = tid >> 4, g = tid & 15;
        if (g < 12) {
            const int uu = g;
            const int t0 = 2 * uu - PAD;
            float a0 = bi2[j], a1 = bi2[j];
            #pragma unroll
            for (int i = 0; i < 4; i++) {
                const float* zrow = z1 + i * 32 + 4 + t0;
                const float* wr = wi2 + (j * 4 + i) * K;
                float v[K + 1];
                #pragma unroll
                for (int jj = 0; jj <= K; jj++) v[jj] = zrow[jj];
                #pragma unroll
                for (int k = 0; k < K; k++) {
                    float w = wr[k];
                    a0 = fmaf(v[k],     w, a0);
                    a1 = fmaf(v[k + 1], w, a1);
                }
            }
            fo[(slot_base + j) * 12 + uu] = 0.5f * (fmaxf(a0, 0.f) + fmaxf(a1, 0.f));
        }
    }
    __syncthreads();
}

__global__ void __launch_bounds__(64) feat_kernel(
    const float* __restrict__ w_hs, const float* __restrict__ b_hs,
    const float* __restrict__ w_ls, const float* __restrict__ b_ls,
    const float* __restrict__ w_hi1, const float* __restrict__ b_hi1,
    const float* __restrict__ w_hi2, const float* __restrict__ b_hi2,
    const float* __restrict__ w_li1, const float* __restrict__ b_li1,
    const float* __restrict__ w_li2, const float* __restrict__ b_li2)
{
    const int c = blockIdx.x;
    const int b = blockIdx.y;
    const int tid = threadIdx.x;

    __shared__ float xs[104];
    __shared__ float hs[8 * 56];
    __shared__ float z1[4 * 32];
    __shared__ float sw_h[8 * 7],       sw_l[8 * 3];
    __shared__ float swi1_h[4 * 8 * 7], swi2_h[4 * 4 * 7];
    __shared__ float swi1_l[4 * 8 * 3], swi2_l[4 * 4 * 3];
    __shared__ float sb_h[8], sb_l[8];
    __shared__ float sbi1_h[4], sbi2_h[4], sbi1_l[4], sbi2_l[4];

    for (int i = tid; i < 8 * 56; i += 64) hs[i] = 0.f;
    for (int i = tid; i < 4 * 32; i += 64) z1[i] = 0.f;
    if (tid < 4) { xs[tid] = 0.f; xs[100 + tid] = 0.f; }

    const float* xrow = g_xt + ((size_t)b * CCH + c) * TLEN;
    for (int i = tid; i < 96; i += 64) xs[4 + i] = xrow[i];
    for (int i = tid; i < 56; i += 64) sw_h[i] = w_hs[i];
    if (tid < 24)                      sw_l[tid] = w_ls[tid];
    if (tid < 8) { sb_h[tid] = b_hs[tid]; sb_l[tid] = b_ls[tid]; }
    for (int i = tid; i < 224; i += 64) swi1_h[i] = w_hi1[c * 224 + i];
    for (int i = tid; i < 112; i += 64) swi2_h[i] = w_hi2[c * 112 + i];
    for (int i = tid; i < 96;  i += 64) swi1_l[i] = w_li1[c * 96 + i];
    if (tid < 48)                       swi2_l[tid] = w_li2[c * 48 + tid];
    if (tid < 4) {
        sbi1_h[tid] = b_hi1[c * 4 + tid];
        sbi2_h[tid] = b_hi2[c * 4 + tid];
        sbi1_l[tid] = b_li1[c * 4 + tid];
        sbi2_l[tid] = b_li2[c * 4 + tid];
    }
    __syncthreads();

    float* fo = g_feat + (size_t)b * FIN + c * 108;
    const float* xsp = xs + 4;

    if (tid < 12) {   // slot 0: mean of 8
        float s = 0.f;
        #pragma unroll
        for (int k = 0; k < 8; k++) s += xsp[tid * 8 + k];
        fo[tid] = s * 0.125f;
    }

    run_branch<3, 1>(xsp, hs, z1, sw_l, sb_l, swi1_l, sbi1_l, swi2_l, sbi2_l, fo, 1, tid);
    run_branch<7, 3>(xsp, hs, z1, sw_h, sb_h, swi1_h, sbi1_h, swi2_h, sbi2_h, fo, 5, tid);
}

// ---------------------------------------------------------------------------
// Split-precision conversions
// ---------------------------------------------------------------------------
__device__ __forceinline__ void split8(const float* v, __nv_bfloat16* hi, __nv_bfloat16* lo) {
    #pragma unroll
    for (int i = 0; i < 8; i++) {
        __nv_bfloat16 h = __float2bfloat16(v[i]);
        hi[i] = h;
        lo[i] = __float2bfloat16(v[i] - __bfloat162float(h));
    }
}

__global__ void __launch_bounds__(256) convA_kernel() {
    const size_t idx = (size_t)blockIdx.x * 256 + threadIdx.x;   // 2048*896
    const int m  = (int)(idx / 896);
    const int kb = (int)(idx % 896);
    const int k0 = kb * 8;
    float v[8];
    if (kb < 891) {
        float4 a = *(const float4*)(g_feat + (size_t)m * FIN + k0);
        float4 b = *(const float4*)(g_feat + (size_t)m * FIN + k0 + 4);
        v[0]=a.x; v[1]=a.y; v[2]=a.z; v[3]=a.w; v[4]=b.x; v[5]=b.y; v[6]=b.z; v[7]=b.w;
    } else {
        #pragma unroll
        for (int i = 0; i < 8; i++) v[i] = 0.f;
    }
    __align__(16) __nv_bfloat16 hi[8], lo[8];
    split8(v, hi, lo);
    __nv_bfloat16* dst = g_A2 + (size_t)m * KP + k0;
    *(uint4*)(dst)            = *(uint4*)hi;
    *(uint4*)(dst + KSEC)     = *(uint4*)hi;
    *(uint4*)(dst + 2 * KSEC) = *(uint4*)lo;
}

__global__ void __launch_bounds__(256) convB_kernel(const float* __restrict__ w1) {
    const size_t idx = (size_t)blockIdx.x * 256 + threadIdx.x;   // 2048*896
    const int n  = (int)(idx / 896);
    const int kb = (int)(idx % 896);
    const int k0 = kb * 8;
    float v[8];
    if (n < HID && kb < 891) {
        float4 a = *(const float4*)(w1 + (size_t)n * FIN + k0);
        float4 b = *(const float4*)(w1 + (size_t)n * FIN + k0 + 4);
        v[0]=a.x; v[1]=a.y; v[2]=a.z; v[3]=a.w; v[4]=b.x; v[5]=b.y; v[6]=b.z; v[7]=b.w;
    } else {
        #pragma unroll
        for (int i = 0; i < 8; i++) v[i] = 0.f;
    }
    __align__(16) __nv_bfloat16 hi[8], lo[8];
    split8(v, hi, lo);
    __nv_bfloat16* dst = g_B2 + (size_t)n * KP + k0;
    *(uint4*)(dst)            = *(uint4*)hi;
    *(uint4*)(dst + KSEC)     = *(uint4*)lo;
    *(uint4*)(dst + 2 * KSEC) = *(uint4*)hi;
}

// ---------------------------------------------------------------------------
// fc1 GEMM (HMMA bf16) — R4-exact: 128x128x32 tile, 256 threads / 8 warps
// (2m x 4n), warp tile 64x32, 4-stage cp.async (64KB), grid 16x16.
// No min-blocks clause (R12 showed it forces spills).
// ---------------------------------------------------------------------------
constexpr int GSTAGES = 4;
constexpr int STAGE_BYTES = 16384;
constexpr int GSMEM_BYTES = GSTAGES * STAGE_BYTES;   // 64 KB

__global__ void __launch_bounds__(256) gemm_kernel(const float* __restrict__ bias) {
    extern __shared__ char smem[];
    const uint32_t smem_u32 = smem_to_u32(smem);
    const int tid  = threadIdx.x;
    const int wid  = tid >> 5;
    const int lane = tid & 31;
    const int bm = blockIdx.y * 128;
    const int bn = blockIdx.x * 128;

    const int warp_m = wid & 1;          // 2 -> 64 rows each
    const int warp_n = wid >> 1;         // 4 -> 32 cols each

    const int lcu  = tid & 3;
    const int lrow = tid >> 2;           // 0..63 ; rows lrow, lrow+64
    const __nv_bfloat16* srcA[2];
    const __nv_bfloat16* srcB[2];
    uint32_t dstA[2], dstB[2];
    #pragma unroll
    for (int i = 0; i < 2; i++) {
        const int r = lrow + 64 * i;
        srcA[i] = g_A2 + (size_t)(bm + r) * KP + lcu * 8;
        srcB[i] = g_B2 + (size_t)(bn + r) * KP + lcu * 8;
        const uint32_t sw = (uint32_t)((lcu ^ ((r >> 1) & 3)) << 4);
        dstA[i] = r * 64 + sw;
        dstB[i] = 8192 + r * 64 + sw;
    }

    const int g8 = lane >> 3;
    const int l8 = lane & 7;
    uint32_t aoff[8];
    #pragma unroll
    for (int mt = 0; mt < 4; mt++) {
        const int mrow = warp_m * 64 + mt * 16 + (g8 & 1) * 8 + l8;
        const int s = (mrow >> 1) & 3;
        #pragma unroll
        for (int ks = 0; ks < 2; ks++) {
            const int cu = 2 * ks + (g8 >> 1);
            aoff[mt * 2 + ks] = mrow * 64 + ((cu ^ s) << 4);
        }
    }
    uint32_t boff[4];
    #pragma unroll
    for (int p = 0; p < 2; p++) {
        const int nrow = warp_n * 32 + p * 16 + (g8 >> 1) * 8 + l8;
        const int s = (nrow >> 1) & 3;
        #pragma unroll
        for (int ks = 0; ks < 2; ks++) {
            const int cu = 2 * ks + (g8 & 1);
            boff[p * 2 + ks] = 8192 + nrow * 64 + ((cu ^ s) << 4);
        }
    }

    float acc[4][4][4];
    #pragma unroll
    for (int mt = 0; mt < 4; mt++)
        #pragma unroll
        for (int nt = 0; nt < 4; nt++)
            #pragma unroll
            for (int e = 0; e < 4; e++) acc[mt][nt][e] = 0.f;

    #pragma unroll
    for (int kt = 0; kt < GSTAGES - 1; kt++) {
        const uint32_t sb = smem_u32 + kt * STAGE_BYTES;
        #pragma unroll
        for (int i = 0; i < 2; i++) {
            cp16(sb + dstA[i], srcA[i] + (size_t)kt * 32);
            cp16(sb + dstB[i], srcB[i] + (size_t)kt * 32);
        }
        CP_COMMIT();
    }

    for (int kt = 0; kt < KT; kt++) {
        CP_WAIT2();
        __syncthreads();

        const int knext = kt + GSTAGES - 1;
        if (knext < KT) {
            const uint32_t sb = smem_u32 + (knext & 3) * STAGE_BYTES;
            #pragma unroll
            for (int i = 0; i < 2; i++) {
                cp16(sb + dstA[i], srcA[i] + (size_t)knext * 32);
                cp16(sb + dstB[i], srcB[i] + (size_t)knext * 32);
            }
        }
        CP_COMMIT();

        const uint32_t sb = smem_u32 + (kt & 3) * STAGE_BYTES;
        #pragma unroll
        for (int ks = 0; ks < 2; ks++) {
            uint32_t afr[4][4], bfr[2][4];
            #pragma unroll
            for (int mt = 0; mt < 4; mt++) ldsm_x4(afr[mt], sb + aoff[mt * 2 + ks]);
            #pragma unroll
            for (int p = 0; p < 2; p++)    ldsm_x4(bfr[p],  sb + boff[p * 2 + ks]);
            #pragma unroll
            for (int mt = 0; mt < 4; mt++)
                #pragma unroll
                for (int nt = 0; nt < 4; nt++)
                    mma16816(acc[mt][nt], afr[mt],
                             bfr[nt >> 1][(nt & 1) * 2],
                             bfr[nt >> 1][(nt & 1) * 2 + 1]);
        }
    }

    const int qrow = lane >> 2;
    const int qcol = (lane & 3) * 2;
    #pragma unroll
    for (int mt = 0; mt < 4; mt++) {
        #pragma unroll
        for (int nt = 0; nt < 4; nt++) {
            const int n = bn + warp_n * 32 + nt * 8 + qcol;
            if (n >= HID) continue;
            const float b0 = bias[n], b1 = bias[n + 1];
            #pragma unroll
            for (int half = 0; half < 2; half++) {
                const int m = bm + warp_m * 64 + mt * 16 + qrow + half * 8;
                float* o = g_h + (size_t)m * HID + n;
                o[0] = fmaxf(acc[mt][nt][half * 2 + 0] + b0, 0.f);
                o[1] = fmaxf(acc[mt][nt][half * 2 + 1] + b1, 0.f);
            }
        }
    }
}

// ---------------------------------------------------------------------------
// fc2: warp-per-row, 14 outputs in registers, g_h read exactly once.
// ---------------------------------------------------------------------------
__global__ void __launch_bounds__(256) fc2_kernel(
    const float* __restrict__ w2, const float* __restrict__ b2,
    float* __restrict__ out)
{
    const int wid  = threadIdx.x >> 5;
    const int lane = threadIdx.x & 31;
    const int m = blockIdx.x * 8 + wid;

    const float* hrow = g_h + (size_t)m * HID;
    float acc[NCLS];
    #pragma unroll
    for (int n = 0; n < NCLS; n++) acc[n] = 0.f;

    for (int k = lane; k < HID; k += 32) {
        const float h = hrow[k];
        #pragma unroll
        for (int n = 0; n < NCLS; n++)
            acc[n] = fmaf(h, w2[n * HID + k], acc[n]);
    }
    #pragma unroll
    for (int n = 0; n < NCLS; n++)
        #pragma unroll
        for (int off = 16; off > 0; off >>= 1)
            acc[n] += __shfl_down_sync(0xffffffffu, acc[n], off);
    if (lane == 0) {
        #pragma unroll
        for (int n = 0; n < NCLS; n++)
            out[m * NCLS + n] = acc[n] + b2[n];
    }
}

// ---------------------------------------------------------------------------
// Entry
// ---------------------------------------------------------------------------
extern "C" void kernel_launch(void* const* d_in, const int* in_sizes, int n_in,
                              void* d_out, int out_size)
{
    const float* x     = (const float*)d_in[0];
    const float* w_hs  = (const float*)d_in[1];
    const float* b_hs  = (const float*)d_in[2];
    const float* w_ls  = (const float*)d_in[3];
    const float* b_ls  = (const float*)d_in[4];
    const float* w_hi1 = (const float*)d_in[5];
    const float* b_hi1 = (const float*)d_in[6];
    const float* w_hi2 = (const float*)d_in[7];
    const float* b_hi2 = (const float*)d_in[8];
    const float* w_li1 = (const float*)d_in[9];
    const float* b_li1 = (const float*)d_in[10];
    const float* w_li2 = (const float*)d_in[11];
    const float* b_li2 = (const float*)d_in[12];
    const float* w_fc1 = (const float*)d_in[13];
    const float* b_fc1 = (const float*)d_in[14];
    const float* w_fc2 = (const float*)d_in[15];
    const float* b_fc2 = (const float*)d_in[16];
    float* out = (float*)d_out;

    static bool attr_set = false;
    if (!attr_set) {
        cudaFuncSetAttribute(gemm_kernel, cudaFuncAttributeMaxDynamicSharedMemorySize,
                             GSMEM_BYTES);
        attr_set = true;
    }

    transpose_kernel<<<BSZ, 256>>>(x);
    convB_kernel<<<(NPAD * 896) / 256, 256>>>(w_fc1);
    feat_kernel<<<dim3(CCH, BSZ), 64>>>(w_hs, b_hs, w_ls, b_ls,
                                        w_hi1, b_hi1, w_hi2, b_hi2,
                                        w_li1, b_li1, w_li2, b_li2);
    convA_kernel<<<(BSZ * 896) / 256, 256>>>();
    gemm_kernel<<<dim3(16, 16), 256, GSMEM_BYTES>>>(b_fc1);
    fc2_kernel<<<BSZ / 8, 256>>>(w_fc2, b_fc2, out);
}

// round 15
// speedup vs baseline: 1.3515x; 1.0225x over previous
#include <cuda_runtime.h>
#include <cuda_bf16.h>
#include <cstdint>

// ---------------------------------------------------------------------------
// Problem constants
// ---------------------------------------------------------------------------
constexpr int CCH   = 66;
constexpr int TLEN  = 96;
constexpr int BSZ   = 2048;
constexpr int FIN   = 9 * CCH * 12;   // 7128
constexpr int HID   = 1936;
constexpr int NCLS  = 14;

// fc1 GEMM padded dims (split bf16: A'=[Ahi|Ahi|Alo], B'=[Bhi|Blo|Bhi])
constexpr int KSEC  = 7168;
constexpr int KP    = 3 * KSEC;       // 21504
constexpr int NPAD  = 2048;
constexpr int KT    = KP / 32;        // 672

// ---------------------------------------------------------------------------
// Scratch
// ---------------------------------------------------------------------------
__device__ __align__(16) float g_xt[(size_t)BSZ * CCH * TLEN];
__device__ __align__(16) float g_feat[(size_t)BSZ * FIN];
__device__ __align__(16) float g_h[(size_t)BSZ * HID];
__device__ __align__(16) __nv_bfloat16 g_A2[(size_t)BSZ * KP];
__device__ __align__(16) __nv_bfloat16 g_B2[(size_t)NPAD * KP];

// ---------------------------------------------------------------------------
// PTX helpers (sm_80+ portable)
// ---------------------------------------------------------------------------
__device__ __forceinline__ uint32_t smem_to_u32(const void* p) {
    uint32_t a;
    asm("{ .reg .u64 t; cvta.to.shared.u64 t, %1; cvt.u32.u64 %0, t; }" : "=r"(a) : "l"(p));
    return a;
}
__device__ __forceinline__ void cp16(uint32_t dst, const void* src) {
    asm volatile("cp.async.cg.shared.global [%0], [%1], 16;" :: "r"(dst), "l"(src));
}
#define CP_COMMIT() asm volatile("cp.async.commit_group;" ::: "memory")
#define CP_WAIT2()  asm volatile("cp.async.wait_group 2;" ::: "memory")

__device__ __forceinline__ void ldsm_x4(uint32_t* r, uint32_t addr) {
    asm volatile("ldmatrix.sync.aligned.m8n8.x4.shared.b16 {%0,%1,%2,%3}, [%4];"
                 : "=r"(r[0]), "=r"(r[1]), "=r"(r[2]), "=r"(r[3]) : "r"(addr));
}
__device__ __forceinline__ void mma16816(float* d, const uint32_t* a,
                                         uint32_t b0, uint32_t b1) {
    asm volatile(
        "mma.sync.aligned.m16n8k16.row.col.f32.bf16.bf16.f32 "
        "{%0,%1,%2,%3}, {%4,%5,%6,%7}, {%8,%9}, {%0,%1,%2,%3};"
        : "+f"(d[0]), "+f"(d[1]), "+f"(d[2]), "+f"(d[3])
        : "r"(a[0]), "r"(a[1]), "r"(a[2]), "r"(a[3]), "r"(b0), "r"(b1));
}

// ---------------------------------------------------------------------------
// Transpose: x (B, T, C) -> g_xt (B, C, T)
// ---------------------------------------------------------------------------
__global__ void __launch_bounds__(256) transpose_kernel(const float* __restrict__ x) {
    __shared__ float s[TLEN * CCH];
    const int b = blockIdx.x;
    const float* src = x + (size_t)b * TLEN * CCH;
    for (int i = threadIdx.x; i < TLEN * CCH; i += 256) s[i] = src[i];
    __syncthreads();
    float* dst = g_xt + (size_t)b * CCH * TLEN;
    for (int i = threadIdx.x; i < TLEN * CCH; i += 256) {
        int c = i / TLEN, t = i - c * TLEN;
        dst[i] = s[t * CCH + c];
    }
}

// ---------------------------------------------------------------------------
// Feature extraction: one 96-thread block per (b, c).
// Latency-balanced mapping: stage1 4 windows/thread (12 lanes per out-row),
// stage2 exactly 1 item/thread (96 items), stage3 1 item for tid<48.
// ---------------------------------------------------------------------------
template<int K, int PAD>
__device__ __forceinline__ void run_branch(
    const float* xsp, float* hs, float* z1,
    const float* ws,  const float* bs,
    const float* wi1, const float* bi1,
    const float* wi2, const float* bi2,
    float* fo, int slot_base, int tid)
{
    {   // stage 1: shared conv 1->8 (96), relu, pool2 -> hs rows of 48
        // 96 threads: o = tid/12 (0..7), g = tid%12 (0..11); 4 windows each.
        const int o = tid / 12, g = tid - o * 12;
        float wreg[K];
        #pragma unroll
        for (int k = 0; k < K; k++) wreg[k] = ws[o * K + k];
        const float bo = bs[o];
        float* hrow = hs + o * 56 + 4;
        #pragma unroll
        for (int d = 0; d < 4; d++) {
            const int uu = g + d * 12;          // 0..47
            const int t0 = 2 * uu - PAD;
            float v[K + 1];
            #pragma unroll
            for (int j = 0; j <= K; j++) v[j] = xsp[t0 + j];
            float a0 = bo, a1 = bo;
            #pragma unroll
            for (int k = 0; k < K; k++) {
                a0 = fmaf(v[k],     wreg[k], a0);
                a1 = fmaf(v[k + 1], wreg[k], a1);
            }
            hrow[uu] = 0.5f * (fmaxf(a0, 0.f) + fmaxf(a1, 0.f));
        }
    }
    __syncthreads();
    {   // stage 2: grouped conv 8->4 (48), relu, pool2 -> z1 rows of 24
        // 96 threads = 96 items: j = tid/24 (0..3), uu = tid%24.
        const int j = tid / 24, uu = tid - j * 24;
        const float bj = bi1[j];
        const float* wbase = wi1 + j * 8 * K;
        const int t0 = 2 * uu - PAD;
        float a0 = bj, a1 = bj;
        #pragma unroll
        for (int i = 0; i < 8; i++) {
            const float* hrow = hs + i * 56 + 4 + t0;
            const float* wr = wbase + i * K;
            float v[K + 1];
            #pragma unroll
            for (int jj = 0; jj <= K; jj++) v[jj] = hrow[jj];
            #pragma unroll
            for (int k = 0; k < K; k++) {
                float w = wr[k];
                a0 = fmaf(v[k],     w, a0);
                a1 = fmaf(v[k + 1], w, a1);
            }
        }
        z1[j * 32 + 4 + uu] = 0.5f * (fmaxf(a0, 0.f) + fmaxf(a1, 0.f));
    }
    __syncthreads();
    {   // stage 3: grouped conv 4->4 (24), relu, pool2 -> 12 outputs
        // 48 items: j = tid/12, uu = tid%12 for tid < 48.
        if (tid < 48) {
            const int j = tid / 12, uu = tid - j * 12;
            const int t0 = 2 * uu - PAD;
            float a0 = bi2[j], a1 = bi2[j];
            #pragma unroll
            for (int i = 0; i < 4; i++) {
                const float* zrow = z1 + i * 32 + 4 + t0;
                const float* wr = wi2 + (j * 4 + i) * K;
                float v[K + 1];
                #pragma unroll
                for (int jj = 0; jj <= K; jj++) v[jj] = zrow[jj];
                #pragma unroll
                for (int k = 0; k < K; k++) {
                    float w = wr[k];
                    a0 = fmaf(v[k],     w, a0);
                    a1 = fmaf(v[k + 1], w, a1);
                }
            }
            fo[(slot_base + j) * 12 + uu] = 0.5f * (fmaxf(a0, 0.f) + fmaxf(a1, 0.f));
        }
    }
    __syncthreads();
}

__global__ void __launch_bounds__(96) feat_kernel(
    const float* __restrict__ w_hs, const float* __restrict__ b_hs,
    const float* __restrict__ w_ls, const float* __restrict__ b_ls,
    const float* __restrict__ w_hi1, const float* __restrict__ b_hi1,
    const float* __restrict__ w_hi2, const float* __restrict__ b_hi2,
    const float* __restrict__ w_li1, const float* __restrict__ b_li1,
    const float* __restrict__ w_li2, const float* __restrict__ b_li2)
{
    const int c = blockIdx.x;
    const int b = blockIdx.y;
    const int tid = threadIdx.x;

    __shared__ float xs[104];
    __shared__ float hs[8 * 56];
    __shared__ float z1[4 * 32];
    __shared__ float sw_h[8 * 7],       sw_l[8 * 3];
    __shared__ float swi1_h[4 * 8 * 7], swi2_h[4 * 4 * 7];
    __shared__ float swi1_l[4 * 8 * 3], swi2_l[4 * 4 * 3];
    __shared__ float sb_h[8], sb_l[8];
    __shared__ float sbi1_h[4], sbi2_h[4], sbi1_l[4], sbi2_l[4];

    for (int i = tid; i < 8 * 56; i += 96) hs[i] = 0.f;
    for (int i = tid; i < 4 * 32; i += 96) z1[i] = 0.f;
    if (tid < 4) { xs[tid] = 0.f; xs[100 + tid] = 0.f; }

    const float* xrow = g_xt + ((size_t)b * CCH + c) * TLEN;
    if (tid < 96) xs[4 + tid] = xrow[tid];
    if (tid < 56) sw_h[tid] = w_hs[tid];
    if (tid < 24) sw_l[tid] = w_ls[tid];
    if (tid < 8) { sb_h[tid] = b_hs[tid]; sb_l[tid] = b_ls[tid]; }
    for (int i = tid; i < 224; i += 96) swi1_h[i] = w_hi1[c * 224 + i];
    for (int i = tid; i < 112; i += 96) swi2_h[i] = w_hi2[c * 112 + i];
    if (tid < 96)                       swi1_l[tid] = w_li1[c * 96 + tid];
    if (tid < 48)                       swi2_l[tid] = w_li2[c * 48 + tid];
    if (tid < 4) {
        sbi1_h[tid] = b_hi1[c * 4 + tid];
        sbi2_h[tid] = b_hi2[c * 4 + tid];
        sbi1_l[tid] = b_li1[c * 4 + tid];
        sbi2_l[tid] = b_li2[c * 4 + tid];
    }
    __syncthreads();

    float* fo = g_feat + (size_t)b * FIN + c * 108;
    const float* xsp = xs + 4;

    if (tid < 12) {   // slot 0: mean of 8
        float s = 0.f;
        #pragma unroll
        for (int k = 0; k < 8; k++) s += xsp[tid * 8 + k];
        fo[tid] = s * 0.125f;
    }

    run_branch<3, 1>(xsp, hs, z1, sw_l, sb_l, swi1_l, sbi1_l, swi2_l, sbi2_l, fo, 1, tid);
    run_branch<7, 3>(xsp, hs, z1, sw_h, sb_h, swi1_h, sbi1_h, swi2_h, sbi2_h, fo, 5, tid);
}

// ---------------------------------------------------------------------------
// Split-precision conversions
// ---------------------------------------------------------------------------
__device__ __forceinline__ void split8(const float* v, __nv_bfloat16* hi, __nv_bfloat16* lo) {
    #pragma unroll
    for (int i = 0; i < 8; i++) {
        __nv_bfloat16 h = __float2bfloat16(v[i]);
        hi[i] = h;
        lo[i] = __float2bfloat16(v[i] - __bfloat162float(h));
    }
}

__global__ void __launch_bounds__(256) convA_kernel() {
    const size_t idx = (size_t)blockIdx.x * 256 + threadIdx.x;   // 2048*896
    const int m  = (int)(idx / 896);
    const int kb = (int)(idx % 896);
    const int k0 = kb * 8;
    float v[8];
    if (kb < 891) {
        float4 a = *(const float4*)(g_feat + (size_t)m * FIN + k0);
        float4 b = *(const float4*)(g_feat + (size_t)m * FIN + k0 + 4);
        v[0]=a.x; v[1]=a.y; v[2]=a.z; v[3]=a.w; v[4]=b.x; v[5]=b.y; v[6]=b.z; v[7]=b.w;
    } else {
        #pragma unroll
        for (int i = 0; i < 8; i++) v[i] = 0.f;
    }
    __align__(16) __nv_bfloat16 hi[8], lo[8];
    split8(v, hi, lo);
    __nv_bfloat16* dst = g_A2 + (size_t)m * KP + k0;
    *(uint4*)(dst)            = *(uint4*)hi;
    *(uint4*)(dst + KSEC)     = *(uint4*)hi;
    *(uint4*)(dst + 2 * KSEC) = *(uint4*)lo;
}

__global__ void __launch_bounds__(256) convB_kernel(const float* __restrict__ w1) {
    const size_t idx = (size_t)blockIdx.x * 256 + threadIdx.x;   // 2048*896
    const int n  = (int)(idx / 896);
    const int kb = (int)(idx % 896);
    const int k0 = kb * 8;
    float v[8];
    if (n < HID && kb < 891) {
        float4 a = *(const float4*)(w1 + (size_t)n * FIN + k0);
        float4 b = *(const float4*)(w1 + (size_t)n * FIN + k0 + 4);
        v[0]=a.x; v[1]=a.y; v[2]=a.z; v[3]=a.w; v[4]=b.x; v[5]=b.y; v[6]=b.z; v[7]=b.w;
    } else {
        #pragma unroll
        for (int i = 0; i < 8; i++) v[i] = 0.f;
    }
    __align__(16) __nv_bfloat16 hi[8], lo[8];
    split8(v, hi, lo);
    __nv_bfloat16* dst = g_B2 + (size_t)n * KP + k0;
    *(uint4*)(dst)            = *(uint4*)hi;
    *(uint4*)(dst + KSEC)     = *(uint4*)lo;
    *(uint4*)(dst + 2 * KSEC) = *(uint4*)hi;
}

// ---------------------------------------------------------------------------
// fc1 GEMM (HMMA bf16) — R4-exact: 128x128x32 tile, 256 threads / 8 warps
// (2m x 4n), warp tile 64x32, 4-stage cp.async (64KB), grid 16x16.
// ---------------------------------------------------------------------------
constexpr int GSTAGES = 4;
constexpr int STAGE_BYTES = 16384;
constexpr int GSMEM_BYTES = GSTAGES * STAGE_BYTES;   // 64 KB

__global__ void __launch_bounds__(256) gemm_kernel(const float* __restrict__ bias) {
    extern __shared__ char smem[];
    const uint32_t smem_u32 = smem_to_u32(smem);
    const int tid  = threadIdx.x;
    const int wid  = tid >> 5;
    const int lane = tid & 31;
    const int bm = blockIdx.y * 128;
    const int bn = blockIdx.x * 128;

    const int warp_m = wid & 1;          // 2 -> 64 rows each
    const int warp_n = wid >> 1;         // 4 -> 32 cols each

    const int lcu  = tid & 3;
    const int lrow = tid >> 2;           // 0..63 ; rows lrow, lrow+64
    const __nv_bfloat16* srcA[2];
    const __nv_bfloat16* srcB[2];
    uint32_t dstA[2], dstB[2];
    #pragma unroll
    for (int i = 0; i < 2; i++) {
        const int r = lrow + 64 * i;
        srcA[i] = g_A2 + (size_t)(bm + r) * KP + lcu * 8;
        srcB[i] = g_B2 + (size_t)(bn + r) * KP + lcu * 8;
        const uint32_t sw = (uint32_t)((lcu ^ ((r >> 1) & 3)) << 4);
        dstA[i] = r * 64 + sw;
        dstB[i] = 8192 + r * 64 + sw;
    }

    const int g8 = lane >> 3;
    const int l8 = lane & 7;
    uint32_t aoff[8];
    #pragma unroll
    for (int mt = 0; mt < 4; mt++) {
        const int mrow = warp_m * 64 + mt * 16 + (g8 & 1) * 8 + l8;
        const int s = (mrow >> 1) & 3;
        #pragma unroll
        for (int ks = 0; ks < 2; ks++) {
            const int cu = 2 * ks + (g8 >> 1);
            aoff[mt * 2 + ks] = mrow * 64 + ((cu ^ s) << 4);
        }
    }
    uint32_t boff[4];
    #pragma unroll
    for (int p = 0; p < 2; p++) {
        const int nrow = warp_n * 32 + p * 16 + (g8 >> 1) * 8 + l8;
        const int s = (nrow >> 1) & 3;
        #pragma unroll
        for (int ks = 0; ks < 2; ks++) {
            const int cu = 2 * ks + (g8 & 1);
            boff[p * 2 + ks] = 8192 + nrow * 64 + ((cu ^ s) << 4);
        }
    }

    float acc[4][4][4];
    #pragma unroll
    for (int mt = 0; mt < 4; mt++)
        #pragma unroll
        for (int nt = 0; nt < 4; nt++)
            #pragma unroll
            for (int e = 0; e < 4; e++) acc[mt][nt][e] = 0.f;

    #pragma unroll
    for (int kt = 0; kt < GSTAGES - 1; kt++) {
        const uint32_t sb = smem_u32 + kt * STAGE_BYTES;
        #pragma unroll
        for (int i = 0; i < 2; i++) {
            cp16(sb + dstA[i], srcA[i] + (size_t)kt * 32);
            cp16(sb + dstB[i], srcB[i] + (size_t)kt * 32);
        }
        CP_COMMIT();
    }

    for (int kt = 0; kt < KT; kt++) {
        CP_WAIT2();
        __syncthreads();

        const int knext = kt + GSTAGES - 1;
        if (knext < KT) {
            const uint32_t sb = smem_u32 + (knext & 3) * STAGE_BYTES;
            #pragma unroll
            for (int i = 0; i < 2; i++) {
                cp16(sb + dstA[i], srcA[i] + (size_t)knext * 32);
                cp16(sb + dstB[i], srcB[i] + (size_t)knext * 32);
            }
        }
        CP_COMMIT();

        const uint32_t sb = smem_u32 + (kt & 3) * STAGE_BYTES;
        #pragma unroll
        for (int ks = 0; ks < 2; ks++) {
            uint32_t afr[4][4], bfr[2][4];
            #pragma unroll
            for (int mt = 0; mt < 4; mt++) ldsm_x4(afr[mt], sb + aoff[mt * 2 + ks]);
            #pragma unroll
            for (int p = 0; p < 2; p++)    ldsm_x4(bfr[p],  sb + boff[p * 2 + ks]);
            #pragma unroll
            for (int mt = 0; mt < 4; mt++)
                #pragma unroll
                for (int nt = 0; nt < 4; nt++)
                    mma16816(acc[mt][nt], afr[mt],
                             bfr[nt >> 1][(nt & 1) * 2],
                             bfr[nt >> 1][(nt & 1) * 2 + 1]);
        }
    }

    const int qrow = lane >> 2;
    const int qcol = (lane & 3) * 2;
    #pragma unroll
    for (int mt = 0; mt < 4; mt++) {
        #pragma unroll
        for (int nt = 0; nt < 4; nt++) {
            const int n = bn + warp_n * 32 + nt * 8 + qcol;
            if (n >= HID) continue;
            const float b0 = bias[n], b1 = bias[n + 1];
            #pragma unroll
            for (int half = 0; half < 2; half++) {
                const int m = bm + warp_m * 64 + mt * 16 + qrow + half * 8;
                float* o = g_h + (size_t)m * HID + n;
                o[0] = fmaxf(acc[mt][nt][half * 2 + 0] + b0, 0.f);
                o[1] = fmaxf(acc[mt][nt][half * 2 + 1] + b1, 0.f);
            }
        }
    }
}

// ---------------------------------------------------------------------------
// fc2: warp-per-row, 14 outputs in registers, g_h read exactly once.
// ---------------------------------------------------------------------------
__global__ void __launch_bounds__(256) fc2_kernel(
    const float* __restrict__ w2, const float* __restrict__ b2,
    float* __restrict__ out)
{
    const int wid  = threadIdx.x >> 5;
    const int lane = threadIdx.x & 31;
    const int m = blockIdx.x * 8 + wid;

    const float* hrow = g_h + (size_t)m * HID;
    float acc[NCLS];
    #pragma unroll
    for (int n = 0; n < NCLS; n++) acc[n] = 0.f;

    for (int k = lane; k < HID; k += 32) {
        const float h = hrow[k];
        #pragma unroll
        for (int n = 0; n < NCLS; n++)
            acc[n] = fmaf(h, w2[n * HID + k], acc[n]);
    }
    #pragma unroll
    for (int n = 0; n < NCLS; n++)
        #pragma unroll
        for (int off = 16; off > 0; off >>= 1)
            acc[n] += __shfl_down_sync(0xffffffffu, acc[n], off);
    if (lane == 0) {
        #pragma unroll
        for (int n = 0; n < NCLS; n++)
            out[m * NCLS + n] = acc[n] + b2[n];
    }
}

// ---------------------------------------------------------------------------
// Entry
// ---------------------------------------------------------------------------
extern "C" void kernel_launch(void* const* d_in, const int* in_sizes, int n_in,
                              void* d_out, int out_size)
{
    const float* x     = (const float*)d_in[0];
    const float* w_hs  = (const float*)d_in[1];
    const float* b_hs  = (const float*)d_in[2];
    const float* w_ls  = (const float*)d_in[3];
    const float* b_ls  = (const float*)d_in[4];
    const float* w_hi1 = (const float*)d_in[5];
    const float* b_hi1 = (const float*)d_in[6];
    const float* w_hi2 = (const float*)d_in[7];
    const float* b_hi2 = (const float*)d_in[8];
    const float* w_li1 = (const float*)d_in[9];
    const float* b_li1 = (const float*)d_in[10];
    const float* w_li2 = (const float*)d_in[11];
    const float* b_li2 = (const float*)d_in[12];
    const float* w_fc1 = (const float*)d_in[13];
    const float* b_fc1 = (const float*)d_in[14];
    const float* w_fc2 = (const float*)d_in[15];
    const float* b_fc2 = (const float*)d_in[16];
    float* out = (float*)d_out;

    static bool attr_set = false;
    if (!attr_set) {
        cudaFuncSetAttribute(gemm_kernel, cudaFuncAttributeMaxDynamicSharedMemorySize,
                             GSMEM_BYTES);
        attr_set = true;
    }

    transpose_kernel<<<BSZ, 256>>>(x);
    convB_kernel<<<(NPAD * 896) / 256, 256>>>(w_fc1);
    feat_kernel<<<dim3(CCH, BSZ), 96>>>(w_hs, b_hs, w_ls, b_ls,
                                        w_hi1, b_hi1, w_hi2, b_hi2,
                                        w_li1, b_li1, w_li2, b_li2);
    convA_kernel<<<(BSZ * 896) / 256, 256>>>();
    gemm_kernel<<<dim3(16, 16), 256, GSMEM_BYTES>>>(b_fc1);
    fc2_kernel<<<BSZ / 8, 256>>>(w_fc2, b_fc2, out);
}

// round 16
// speedup vs baseline: 1.3768x; 1.0187x over previous
#include <cuda_runtime.h>
#include <cuda_bf16.h>
#include <cstdint>

// ---------------------------------------------------------------------------
// Problem constants
// ---------------------------------------------------------------------------
constexpr int CCH   = 66;
constexpr int TLEN  = 96;
constexpr int BSZ   = 2048;
constexpr int FIN   = 9 * CCH * 12;   // 7128
constexpr int HID   = 1936;
constexpr int NCLS  = 14;
constexpr int HB    = BSZ / 2;        // 1024 (batch half)

// fc1 GEMM padded dims (split bf16: A'=[Ahi|Ahi|Alo], B'=[Bhi|Blo|Bhi])
constexpr int KSEC  = 7168;
constexpr int KP    = 3 * KSEC;       // 21504
constexpr int NPAD  = 2048;
constexpr int KT    = KP / 32;        // 672

// ---------------------------------------------------------------------------
// Scratch
// ---------------------------------------------------------------------------
__device__ __align__(16) float g_xt[(size_t)BSZ * CCH * TLEN];
__device__ __align__(16) float g_feat[(size_t)BSZ * FIN];
__device__ __align__(16) float g_h[(size_t)BSZ * HID];
__device__ __align__(16) __nv_bfloat16 g_A2[(size_t)BSZ * KP];
__device__ __align__(16) __nv_bfloat16 g_B2[(size_t)NPAD * KP];

// ---------------------------------------------------------------------------
// PTX helpers (sm_80+ portable)
// ---------------------------------------------------------------------------
__device__ __forceinline__ uint32_t smem_to_u32(const void* p) {
    uint32_t a;
    asm("{ .reg .u64 t; cvta.to.shared.u64 t, %1; cvt.u32.u64 %0, t; }" : "=r"(a) : "l"(p));
    return a;
}
__device__ __forceinline__ void cp16(uint32_t dst, const void* src) {
    asm volatile("cp.async.cg.shared.global [%0], [%1], 16;" :: "r"(dst), "l"(src));
}
#define CP_COMMIT() asm volatile("cp.async.commit_group;" ::: "memory")
#define CP_WAIT2()  asm volatile("cp.async.wait_group 2;" ::: "memory")

__device__ __forceinline__ void ldsm_x4(uint32_t* r, uint32_t addr) {
    asm volatile("ldmatrix.sync.aligned.m8n8.x4.shared.b16 {%0,%1,%2,%3}, [%4];"
                 : "=r"(r[0]), "=r"(r[1]), "=r"(r[2]), "=r"(r[3]) : "r"(addr));
}
__device__ __forceinline__ void mma16816(float* d, const uint32_t* a,
                                         uint32_t b0, uint32_t b1) {
    asm volatile(
        "mma.sync.aligned.m16n8k16.row.col.f32.bf16.bf16.f32 "
        "{%0,%1,%2,%3}, {%4,%5,%6,%7}, {%8,%9}, {%0,%1,%2,%3};"
        : "+f"(d[0]), "+f"(d[1]), "+f"(d[2]), "+f"(d[3])
        : "r"(a[0]), "r"(a[1]), "r"(a[2]), "r"(a[3]), "r"(b0), "r"(b1));
}

// ---------------------------------------------------------------------------
// Transpose: x (B, T, C) -> g_xt (B, C, T), batch range [b0, b0+HB)
// ---------------------------------------------------------------------------
__global__ void __launch_bounds__(256) transpose_kernel(const float* __restrict__ x,
                                                        int b0) {
    __shared__ float s[TLEN * CCH];
    const int b = b0 + blockIdx.x;
    const float* src = x + (size_t)b * TLEN * CCH;
    for (int i = threadIdx.x; i < TLEN * CCH; i += 256) s[i] = src[i];
    __syncthreads();
    float* dst = g_xt + (size_t)b * CCH * TLEN;
    for (int i = threadIdx.x; i < TLEN * CCH; i += 256) {
        int c = i / TLEN, t = i - c * TLEN;
        dst[i] = s[t * CCH + c];
    }
}

// ---------------------------------------------------------------------------
// Feature extraction: one 96-thread block per (b, c). R15 mapping.
// ---------------------------------------------------------------------------
template<int K, int PAD>
__device__ __forceinline__ void run_branch(
    const float* xsp, float* hs, float* z1,
    const float* ws,  const float* bs,
    const float* wi1, const float* bi1,
    const float* wi2, const float* bi2,
    float* fo, int slot_base, int tid)
{
    {   // stage 1: shared conv 1->8 (96), relu, pool2 -> hs rows of 48
        const int o = tid / 12, g = tid - o * 12;
        float wreg[K];
        #pragma unroll
        for (int k = 0; k < K; k++) wreg[k] = ws[o * K + k];
        const float bo = bs[o];
        float* hrow = hs + o * 56 + 4;
        #pragma unroll
        for (int d = 0; d < 4; d++) {
            const int uu = g + d * 12;
            const int t0 = 2 * uu - PAD;
            float v[K + 1];
            #pragma unroll
            for (int j = 0; j <= K; j++) v[j] = xsp[t0 + j];
            float a0 = bo, a1 = bo;
            #pragma unroll
            for (int k = 0; k < K; k++) {
                a0 = fmaf(v[k],     wreg[k], a0);
                a1 = fmaf(v[k + 1], wreg[k], a1);
            }
            hrow[uu] = 0.5f * (fmaxf(a0, 0.f) + fmaxf(a1, 0.f));
        }
    }
    __syncthreads();
    {   // stage 2: grouped conv 8->4 (48), relu, pool2 -> z1 rows of 24
        const int j = tid / 24, uu = tid - j * 24;
        const float bj = bi1[j];
        const float* wbase = wi1 + j * 8 * K;
        const int t0 = 2 * uu - PAD;
        float a0 = bj, a1 = bj;
        #pragma unroll
        for (int i = 0; i < 8; i++) {
            const float* hrow = hs + i * 56 + 4 + t0;
            const float* wr = wbase + i * K;
            float v[K + 1];
            #pragma unroll
            for (int jj = 0; jj <= K; jj++) v[jj] = hrow[jj];
            #pragma unroll
            for (int k = 0; k < K; k++) {
                float w = wr[k];
                a0 = fmaf(v[k],     w, a0);
                a1 = fmaf(v[k + 1], w, a1);
            }
        }
        z1[j * 32 + 4 + uu] = 0.5f * (fmaxf(a0, 0.f) + fmaxf(a1, 0.f));
    }
    __syncthreads();
    {   // stage 3: grouped conv 4->4 (24), relu, pool2 -> 12 outputs
        if (tid < 48) {
            const int j = tid / 12, uu = tid - j * 12;
            const int t0 = 2 * uu - PAD;
            float a0 = bi2[j], a1 = bi2[j];
            #pragma unroll
            for (int i = 0; i < 4; i++) {
                const float* zrow = z1 + i * 32 + 4 + t0;
                const float* wr = wi2 + (j * 4 + i) * K;
                float v[K + 1];
                #pragma unroll
                for (int jj = 0; jj <= K; jj++) v[jj] = zrow[jj];
                #pragma unroll
                for (int k = 0; k < K; k++) {
                    float w = wr[k];
                    a0 = fmaf(v[k],     w, a0);
                    a1 = fmaf(v[k + 1], w, a1);
                }
            }
            fo[(slot_base + j) * 12 + uu] = 0.5f * (fmaxf(a0, 0.f) + fmaxf(a1, 0.f));
        }
    }
    __syncthreads();
}

__global__ void __launch_bounds__(96) feat_kernel(
    const float* __restrict__ w_hs, const float* __restrict__ b_hs,
    const float* __restrict__ w_ls, const float* __restrict__ b_ls,
    const float* __restrict__ w_hi1, const float* __restrict__ b_hi1,
    const float* __restrict__ w_hi2, const float* __restrict__ b_hi2,
    const float* __restrict__ w_li1, const float* __restrict__ b_li1,
    const float* __restrict__ w_li2, const float* __restrict__ b_li2,
    int b0)
{
    const int c = blockIdx.x;
    const int b = b0 + blockIdx.y;
    const int tid = threadIdx.x;

    __shared__ float xs[104];
    __shared__ float hs[8 * 56];
    __shared__ float z1[4 * 32];
    __shared__ float sw_h[8 * 7],       sw_l[8 * 3];
    __shared__ float swi1_h[4 * 8 * 7], swi2_h[4 * 4 * 7];
    __shared__ float swi1_l[4 * 8 * 3], swi2_l[4 * 4 * 3];
    __shared__ float sb_h[8], sb_l[8];
    __shared__ float sbi1_h[4], sbi2_h[4], sbi1_l[4], sbi2_l[4];

    for (int i = tid; i < 8 * 56; i += 96) hs[i] = 0.f;
    for (int i = tid; i < 4 * 32; i += 96) z1[i] = 0.f;
    if (tid < 4) { xs[tid] = 0.f; xs[100 + tid] = 0.f; }

    const float* xrow = g_xt + ((size_t)b * CCH + c) * TLEN;
    if (tid < 96) xs[4 + tid] = xrow[tid];
    if (tid < 56) sw_h[tid] = w_hs[tid];
    if (tid < 24) sw_l[tid] = w_ls[tid];
    if (tid < 8) { sb_h[tid] = b_hs[tid]; sb_l[tid] = b_ls[tid]; }
    for (int i = tid; i < 224; i += 96) swi1_h[i] = w_hi1[c * 224 + i];
    for (int i = tid; i < 112; i += 96) swi2_h[i] = w_hi2[c * 112 + i];
    if (tid < 96)                       swi1_l[tid] = w_li1[c * 96 + tid];
    if (tid < 48)                       swi2_l[tid] = w_li2[c * 48 + tid];
    if (tid < 4) {
        sbi1_h[tid] = b_hi1[c * 4 + tid];
        sbi2_h[tid] = b_hi2[c * 4 + tid];
        sbi1_l[tid] = b_li1[c * 4 + tid];
        sbi2_l[tid] = b_li2[c * 4 + tid];
    }
    __syncthreads();

    float* fo = g_feat + (size_t)b * FIN + c * 108;
    const float* xsp = xs + 4;

    if (tid < 12) {   // slot 0: mean of 8
        float s = 0.f;
        #pragma unroll
        for (int k = 0; k < 8; k++) s += xsp[tid * 8 + k];
        fo[tid] = s * 0.125f;
    }

    run_branch<3, 1>(xsp, hs, z1, sw_l, sb_l, swi1_l, sbi1_l, swi2_l, sbi2_l, fo, 1, tid);
    run_branch<7, 3>(xsp, hs, z1, sw_h, sb_h, swi1_h, sbi1_h, swi2_h, sbi2_h, fo, 5, tid);
}

// ---------------------------------------------------------------------------
// Split-precision conversions
// ---------------------------------------------------------------------------
__device__ __forceinline__ void split8(const float* v, __nv_bfloat16* hi, __nv_bfloat16* lo) {
    #pragma unroll
    for (int i = 0; i < 8; i++) {
        __nv_bfloat16 h = __float2bfloat16(v[i]);
        hi[i] = h;
        lo[i] = __float2bfloat16(v[i] - __bfloat162float(h));
    }
}

__global__ void __launch_bounds__(256) convA_kernel(int m0) {
    const size_t idx = (size_t)blockIdx.x * 256 + threadIdx.x;   // HB*896
    const int m  = m0 + (int)(idx / 896);
    const int kb = (int)(idx % 896);
    const int k0 = kb * 8;
    float v[8];
    if (kb < 891) {
        float4 a = *(const float4*)(g_feat + (size_t)m * FIN + k0);
        float4 b = *(const float4*)(g_feat + (size_t)m * FIN + k0 + 4);
        v[0]=a.x; v[1]=a.y; v[2]=a.z; v[3]=a.w; v[4]=b.x; v[5]=b.y; v[6]=b.z; v[7]=b.w;
    } else {
        #pragma unroll
        for (int i = 0; i < 8; i++) v[i] = 0.f;
    }
    __align__(16) __nv_bfloat16 hi[8], lo[8];
    split8(v, hi, lo);
    __nv_bfloat16* dst = g_A2 + (size_t)m * KP + k0;
    *(uint4*)(dst)            = *(uint4*)hi;
    *(uint4*)(dst + KSEC)     = *(uint4*)hi;
    *(uint4*)(dst + 2 * KSEC) = *(uint4*)lo;
}

__global__ void __launch_bounds__(256) convB_kernel(const float* __restrict__ w1) {
    const size_t idx = (size_t)blockIdx.x * 256 + threadIdx.x;   // 2048*896
    const int n  = (int)(idx / 896);
    const int kb = (int)(idx % 896);
    const int k0 = kb * 8;
    float v[8];
    if (n < HID && kb < 891) {
        float4 a = *(const float4*)(w1 + (size_t)n * FIN + k0);
        float4 b = *(const float4*)(w1 + (size_t)n * FIN + k0 + 4);
        v[0]=a.x; v[1]=a.y; v[2]=a.z; v[3]=a.w; v[4]=b.x; v[5]=b.y; v[6]=b.z; v[7]=b.w;
    } else {
        #pragma unroll
        for (int i = 0; i < 8; i++) v[i] = 0.f;
    }
    __align__(16) __nv_bfloat16 hi[8], lo[8];
    split8(v, hi, lo);
    __nv_bfloat16* dst = g_B2 + (size_t)n * KP + k0;
    *(uint4*)(dst)            = *(uint4*)hi;
    *(uint4*)(dst + KSEC)     = *(uint4*)lo;
    *(uint4*)(dst + 2 * KSEC) = *(uint4*)hi;
}

// ---------------------------------------------------------------------------
// fc1 GEMM (HMMA bf16) — R4-exact kernel, M-offset for half launches:
// 128x128x32 tile, 256 threads / 8 warps (2m x 4n), 4-stage cp.async (64KB).
// ---------------------------------------------------------------------------
constexpr int GSTAGES = 4;
constexpr int STAGE_BYTES = 16384;
constexpr int GSMEM_BYTES = GSTAGES * STAGE_BYTES;   // 64 KB

__global__ void __launch_bounds__(256) gemm_kernel(const float* __restrict__ bias,
                                                   int bm0) {
    extern __shared__ char smem[];
    const uint32_t smem_u32 = smem_to_u32(smem);
    const int tid  = threadIdx.x;
    const int wid  = tid >> 5;
    const int lane = tid & 31;
    const int bm = bm0 + blockIdx.y * 128;
    const int bn = blockIdx.x * 128;

    const int warp_m = wid & 1;
    const int warp_n = wid >> 1;

    const int lcu  = tid & 3;
    const int lrow = tid >> 2;
    const __nv_bfloat16* srcA[2];
    const __nv_bfloat16* srcB[2];
    uint32_t dstA[2], dstB[2];
    #pragma unroll
    for (int i = 0; i < 2; i++) {
        const int r = lrow + 64 * i;
        srcA[i] = g_A2 + (size_t)(bm + r) * KP + lcu * 8;
        srcB[i] = g_B2 + (size_t)(bn + r) * KP + lcu * 8;
        const uint32_t sw = (uint32_t)((lcu ^ ((r >> 1) & 3)) << 4);
        dstA[i] = r * 64 + sw;
        dstB[i] = 8192 + r * 64 + sw;
    }

    const int g8 = lane >> 3;
    const int l8 = lane & 7;
    uint32_t aoff[8];
    #pragma unroll
    for (int mt = 0; mt < 4; mt++) {
        const int mrow = warp_m * 64 + mt * 16 + (g8 & 1) * 8 + l8;
        const int s = (mrow >> 1) & 3;
        #pragma unroll
        for (int ks = 0; ks < 2; ks++) {
            const int cu = 2 * ks + (g8 >> 1);
            aoff[mt * 2 + ks] = mrow * 64 + ((cu ^ s) << 4);
        }
    }
    uint32_t boff[4];
    #pragma unroll
    for (int p = 0; p < 2; p++) {
        const int nrow = warp_n * 32 + p * 16 + (g8 >> 1) * 8 + l8;
        const int s = (nrow >> 1) & 3;
        #pragma unroll
        for (int ks = 0; ks < 2; ks++) {
            const int cu = 2 * ks + (g8 & 1);
            boff[p * 2 + ks] = 8192 + nrow * 64 + ((cu ^ s) << 4);
        }
    }

    float acc[4][4][4];
    #pragma unroll
    for (int mt = 0; mt < 4; mt++)
        #pragma unroll
        for (int nt = 0; nt < 4; nt++)
            #pragma unroll
            for (int e = 0; e < 4; e++) acc[mt][nt][e] = 0.f;

    #pragma unroll
    for (int kt = 0; kt < GSTAGES - 1; kt++) {
        const uint32_t sb = smem_u32 + kt * STAGE_BYTES;
        #pragma unroll
        for (int i = 0; i < 2; i++) {
            cp16(sb + dstA[i], srcA[i] + (size_t)kt * 32);
            cp16(sb + dstB[i], srcB[i] + (size_t)kt * 32);
        }
        CP_COMMIT();
    }

    for (int kt = 0; kt < KT; kt++) {
        CP_WAIT2();
        __syncthreads();

        const int knext = kt + GSTAGES - 1;
        if (knext < KT) {
            const uint32_t sb = smem_u32 + (knext & 3) * STAGE_BYTES;
            #pragma unroll
            for (int i = 0; i < 2; i++) {
                cp16(sb + dstA[i], srcA[i] + (size_t)knext * 32);
                cp16(sb + dstB[i], srcB[i] + (size_t)knext * 32);
            }
        }
        CP_COMMIT();

        const uint32_t sb = smem_u32 + (kt & 3) * STAGE_BYTES;
        #pragma unroll
        for (int ks = 0; ks < 2; ks++) {
            uint32_t afr[4][4], bfr[2][4];
            #pragma unroll
            for (int mt = 0; mt < 4; mt++) ldsm_x4(afr[mt], sb + aoff[mt * 2 + ks]);
            #pragma unroll
            for (int p = 0; p < 2; p++)    ldsm_x4(bfr[p],  sb + boff[p * 2 + ks]);
            #pragma unroll
            for (int mt = 0; mt < 4; mt++)
                #pragma unroll
                for (int nt = 0; nt < 4; nt++)
                    mma16816(acc[mt][nt], afr[mt],
                             bfr[nt >> 1][(nt & 1) * 2],
                             bfr[nt >> 1][(nt & 1) * 2 + 1]);
        }
    }

    const int qrow = lane >> 2;
    const int qcol = (lane & 3) * 2;
    #pragma unroll
    for (int mt = 0; mt < 4; mt++) {
        #pragma unroll
        for (int nt = 0; nt < 4; nt++) {
            const int n = bn + warp_n * 32 + nt * 8 + qcol;
            if (n >= HID) continue;
            const float b0 = bias[n], b1 = bias[n + 1];
            #pragma unroll
            for (int half = 0; half < 2; half++) {
                const int m = bm + warp_m * 64 + mt * 16 + qrow + half * 8;
                float* o = g_h + (size_t)m * HID + n;
                o[0] = fmaxf(acc[mt][nt][half * 2 + 0] + b0, 0.f);
                o[1] = fmaxf(acc[mt][nt][half * 2 + 1] + b1, 0.f);
            }
        }
    }
}

// ---------------------------------------------------------------------------
// fc2: warp-per-row, 14 outputs in registers.
// ---------------------------------------------------------------------------
__global__ void __launch_bounds__(256) fc2_kernel(
    const float* __restrict__ w2, const float* __restrict__ b2,
    float* __restrict__ out)
{
    const int wid  = threadIdx.x >> 5;
    const int lane = threadIdx.x & 31;
    const int m = blockIdx.x * 8 + wid;

    const float* hrow = g_h + (size_t)m * HID;
    float acc[NCLS];
    #pragma unroll
    for (int n = 0; n < NCLS; n++) acc[n] = 0.f;

    for (int k = lane; k < HID; k += 32) {
        const float h = hrow[k];
        #pragma unroll
        for (int n = 0; n < NCLS; n++)
            acc[n] = fmaf(h, w2[n * HID + k], acc[n]);
    }
    #pragma unroll
    for (int n = 0; n < NCLS; n++)
        #pragma unroll
        for (int off = 16; off > 0; off >>= 1)
            acc[n] += __shfl_down_sync(0xffffffffu, acc[n], off);
    if (lane == 0) {
        #pragma unroll
        for (int n = 0; n < NCLS; n++)
            out[m * NCLS + n] = acc[n] + b2[n];
    }
}

// ---------------------------------------------------------------------------
// Entry — two-stream fork/join pipeline (graph-capturable):
//   s1: transpose(h0) -> feat(h0) -> convA(h0)           -> e1
//   s2: convB -> eB -> transpose(h1) -> feat(h1) -> convA(h1) -> e2
//   default: wait(e1,eB) -> gemm(h0) -> wait(e2) -> gemm(h1) -> fc2
// ---------------------------------------------------------------------------
extern "C" void kernel_launch(void* const* d_in, const int* in_sizes, int n_in,
                              void* d_out, int out_size)
{
    const float* x     = (const float*)d_in[0];
    const float* w_hs  = (const float*)d_in[1];
    const float* b_hs  = (const float*)d_in[2];
    const float* w_ls  = (const float*)d_in[3];
    const float* b_ls  = (const float*)d_in[4];
    const float* w_hi1 = (const float*)d_in[5];
    const float* b_hi1 = (const float*)d_in[6];
    const float* w_hi2 = (const float*)d_in[7];
    const float* b_hi2 = (const float*)d_in[8];
    const float* w_li1 = (const float*)d_in[9];
    const float* b_li1 = (const float*)d_in[10];
    const float* w_li2 = (const float*)d_in[11];
    const float* b_li2 = (const float*)d_in[12];
    const float* w_fc1 = (const float*)d_in[13];
    const float* b_fc1 = (const float*)d_in[14];
    const float* w_fc2 = (const float*)d_in[15];
    const float* b_fc2 = (const float*)d_in[16];
    float* out = (float*)d_out;

    static cudaStream_t s1 = nullptr, s2 = nullptr;
    static cudaEvent_t eRoot, e1, e2, eB;
    if (!s1) {
        cudaStreamCreateWithFlags(&s1, cudaStreamNonBlocking);
        cudaStreamCreateWithFlags(&s2, cudaStreamNonBlocking);
        cudaEventCreateWithFlags(&eRoot, cudaEventDisableTiming);
        cudaEventCreateWithFlags(&e1,    cudaEventDisableTiming);
        cudaEventCreateWithFlags(&e2,    cudaEventDisableTiming);
        cudaEventCreateWithFlags(&eB,    cudaEventDisableTiming);
        cudaFuncSetAttribute(gemm_kernel, cudaFuncAttributeMaxDynamicSharedMemorySize,
                             GSMEM_BYTES);
    }

    // fork from the (captured) default stream
    cudaEventRecord(eRoot, 0);
    cudaStreamWaitEvent(s1, eRoot, 0);
    cudaStreamWaitEvent(s2, eRoot, 0);

    // s1: half-0 feature chain
    transpose_kernel<<<HB, 256, 0, s1>>>(x, 0);
    feat_kernel<<<dim3(CCH, HB), 96, 0, s1>>>(w_hs, b_hs, w_ls, b_ls,
                                              w_hi1, b_hi1, w_hi2, b_hi2,
                                              w_li1, b_li1, w_li2, b_li2, 0);
    convA_kernel<<<(HB * 896) / 256, 256, 0, s1>>>(0);
    cudaEventRecord(e1, s1);

    // s2: convB first (needed by gemm h0), then half-1 feature chain
    convB_kernel<<<(NPAD * 896) / 256, 256, 0, s2>>>(w_fc1);
    cudaEventRecord(eB, s2);
    transpose_kernel<<<HB, 256, 0, s2>>>(x, HB);
    feat_kernel<<<dim3(CCH, HB), 96, 0, s2>>>(w_hs, b_hs, w_ls, b_ls,
                                              w_hi1, b_hi1, w_hi2, b_hi2,
                                              w_li1, b_li1, w_li2, b_li2, HB);
    convA_kernel<<<(HB * 896) / 256, 256, 0, s2>>>(HB);
    cudaEventRecord(e2, s2);

    // default: gemm halves as dependencies resolve, then fc2
    cudaStreamWaitEvent(0, e1, 0);
    cudaStreamWaitEvent(0, eB, 0);
    gemm_kernel<<<dim3(16, 8), 256, GSMEM_BYTES>>>(b_fc1, 0);
    cudaStreamWaitEvent(0, e2, 0);
    gemm_kernel<<<dim3(16, 8), 256, GSMEM_BYTES>>>(b_fc1, HB);
    fc2_kernel<<<BSZ / 8, 256>>>(w_fc2, b_fc2, out);
}

// round 17
// speedup vs baseline: 1.4365x; 1.0434x over previous
#include <cuda_runtime.h>
#include <cuda_bf16.h>
#include <cstdint>

// ---------------------------------------------------------------------------
// Problem constants
// ---------------------------------------------------------------------------
constexpr int CCH   = 66;
constexpr int TLEN  = 96;
constexpr int BSZ   = 2048;
constexpr int FIN   = 9 * CCH * 12;   // 7128
constexpr int HID   = 1936;
constexpr int NCLS  = 14;
constexpr int HB    = BSZ / 2;        // 1024 (batch half)

// fc1 GEMM padded dims (split bf16: A'=[Ahi|Ahi|Alo], B'=[Bhi|Blo|Bhi])
constexpr int KSEC  = 7168;
constexpr int KP    = 3 * KSEC;       // 21504
constexpr int NPAD  = 2048;
constexpr int KT    = KP / 32;        // 672

// ---------------------------------------------------------------------------
// Scratch
// ---------------------------------------------------------------------------
__device__ __align__(16) float g_xt[(size_t)BSZ * CCH * TLEN];
__device__ __align__(16) float g_feat[(size_t)BSZ * FIN];
__device__ __align__(16) float g_h[(size_t)BSZ * HID];
__device__ __align__(16) __nv_bfloat16 g_A2[(size_t)BSZ * KP];
__device__ __align__(16) __nv_bfloat16 g_B2[(size_t)NPAD * KP];

// ---------------------------------------------------------------------------
// PTX helpers (sm_80+ portable)
// ---------------------------------------------------------------------------
__device__ __forceinline__ uint32_t smem_to_u32(const void* p) {
    uint32_t a;
    asm("{ .reg .u64 t; cvta.to.shared.u64 t, %1; cvt.u32.u64 %0, t; }" : "=r"(a) : "l"(p));
    return a;
}
__device__ __forceinline__ void cp16(uint32_t dst, const void* src) {
    asm volatile("cp.async.cg.shared.global [%0], [%1], 16;" :: "r"(dst), "l"(src));
}
#define CP_COMMIT() asm volatile("cp.async.commit_group;" ::: "memory")
#define CP_WAIT2()  asm volatile("cp.async.wait_group 2;" ::: "memory")

__device__ __forceinline__ void ldsm_x4(uint32_t* r, uint32_t addr) {
    asm volatile("ldmatrix.sync.aligned.m8n8.x4.shared.b16 {%0,%1,%2,%3}, [%4];"
                 : "=r"(r[0]), "=r"(r[1]), "=r"(r[2]), "=r"(r[3]) : "r"(addr));
}
__device__ __forceinline__ void mma16816(float* d, const uint32_t* a,
                                         uint32_t b0, uint32_t b1) {
    asm volatile(
        "mma.sync.aligned.m16n8k16.row.col.f32.bf16.bf16.f32 "
        "{%0,%1,%2,%3}, {%4,%5,%6,%7}, {%8,%9}, {%0,%1,%2,%3};"
        : "+f"(d[0]), "+f"(d[1]), "+f"(d[2]), "+f"(d[3])
        : "r"(a[0]), "r"(a[1]), "r"(a[2]), "r"(a[3]), "r"(b0), "r"(b1));
}

// ---------------------------------------------------------------------------
// Transpose: x (B, T, C) -> g_xt (B, C, T), batch range [b0, b0+HB)
// ---------------------------------------------------------------------------
__global__ void __launch_bounds__(256) transpose_kernel(const float* __restrict__ x,
                                                        int b0) {
    __shared__ float s[TLEN * CCH];
    const int b = b0 + blockIdx.x;
    const float* src = x + (size_t)b * TLEN * CCH;
    for (int i = threadIdx.x; i < TLEN * CCH; i += 256) s[i] = src[i];
    __syncthreads();
    float* dst = g_xt + (size_t)b * CCH * TLEN;
    for (int i = threadIdx.x; i < TLEN * CCH; i += 256) {
        int c = i / TLEN, t = i - c * TLEN;
        dst[i] = s[t * CCH + c];
    }
}

// ---------------------------------------------------------------------------
// Feature extraction: one 96-thread block per (b, c). R15 mapping.
// ---------------------------------------------------------------------------
template<int K, int PAD>
__device__ __forceinline__ void run_branch(
    const float* xsp, float* hs, float* z1,
    const float* ws,  const float* bs,
    const float* wi1, const float* bi1,
    const float* wi2, const float* bi2,
    float* fo, int slot_base, int tid)
{
    {   // stage 1: shared conv 1->8 (96), relu, pool2 -> hs rows of 48
        const int o = tid / 12, g = tid - o * 12;
        float wreg[K];
        #pragma unroll
        for (int k = 0; k < K; k++) wreg[k] = ws[o * K + k];
        const float bo = bs[o];
        float* hrow = hs + o * 56 + 4;
        #pragma unroll
        for (int d = 0; d < 4; d++) {
            const int uu = g + d * 12;
            const int t0 = 2 * uu - PAD;
            float v[K + 1];
            #pragma unroll
            for (int j = 0; j <= K; j++) v[j] = xsp[t0 + j];
            float a0 = bo, a1 = bo;
            #pragma unroll
            for (int k = 0; k < K; k++) {
                a0 = fmaf(v[k],     wreg[k], a0);
                a1 = fmaf(v[k + 1], wreg[k], a1);
            }
            hrow[uu] = 0.5f * (fmaxf(a0, 0.f) + fmaxf(a1, 0.f));
        }
    }
    __syncthreads();
    {   // stage 2: grouped conv 8->4 (48), relu, pool2 -> z1 rows of 24
        const int j = tid / 24, uu = tid - j * 24;
        const float bj = bi1[j];
        const float* wbase = wi1 + j * 8 * K;
        const int t0 = 2 * uu - PAD;
        float a0 = bj, a1 = bj;
        #pragma unroll
        for (int i = 0; i < 8; i++) {
            const float* hrow = hs + i * 56 + 4 + t0;
            const float* wr = wbase + i * K;
            float v[K + 1];
            #pragma unroll
            for (int jj = 0; jj <= K; jj++) v[jj] = hrow[jj];
            #pragma unroll
            for (int k = 0; k < K; k++) {
                float w = wr[k];
                a0 = fmaf(v[k],     w, a0);
                a1 = fmaf(v[k + 1], w, a1);
            }
        }
        z1[j * 32 + 4 + uu] = 0.5f * (fmaxf(a0, 0.f) + fmaxf(a1, 0.f));
    }
    __syncthreads();
    {   // stage 3: grouped conv 4->4 (24), relu, pool2 -> 12 outputs
        if (tid < 48) {
            const int j = tid / 12, uu = tid - j * 12;
            const int t0 = 2 * uu - PAD;
            float a0 = bi2[j], a1 = bi2[j];
            #pragma unroll
            for (int i = 0; i < 4; i++) {
                const float* zrow = z1 + i * 32 + 4 + t0;
                const float* wr = wi2 + (j * 4 + i) * K;
                float v[K + 1];
                #pragma unroll
                for (int jj = 0; jj <= K; jj++) v[jj] = zrow[jj];
                #pragma unroll
                for (int k = 0; k < K; k++) {
                    float w = wr[k];
                    a0 = fmaf(v[k],     w, a0);
                    a1 = fmaf(v[k + 1], w, a1);
                }
            }
            fo[(slot_base + j) * 12 + uu] = 0.5f * (fmaxf(a0, 0.f) + fmaxf(a1, 0.f));
        }
    }
    __syncthreads();
}

__global__ void __launch_bounds__(96) feat_kernel(
    const float* __restrict__ w_hs, const float* __restrict__ b_hs,
    const float* __restrict__ w_ls, const float* __restrict__ b_ls,
    const float* __restrict__ w_hi1, const float* __restrict__ b_hi1,
    const float* __restrict__ w_hi2, const float* __restrict__ b_hi2,
    const float* __restrict__ w_li1, const float* __restrict__ b_li1,
    const float* __restrict__ w_li2, const float* __restrict__ b_li2,
    int b0)
{
    const int c = blockIdx.x;
    const int b = b0 + blockIdx.y;
    const int tid = threadIdx.x;

    __shared__ float xs[104];
    __shared__ float hs[8 * 56];
    __shared__ float z1[4 * 32];
    __shared__ float sw_h[8 * 7],       sw_l[8 * 3];
    __shared__ float swi1_h[4 * 8 * 7], swi2_h[4 * 4 * 7];
    __shared__ float swi1_l[4 * 8 * 3], swi2_l[4 * 4 * 3];
    __shared__ float sb_h[8], sb_l[8];
    __shared__ float sbi1_h[4], sbi2_h[4], sbi1_l[4], sbi2_l[4];

    for (int i = tid; i < 8 * 56; i += 96) hs[i] = 0.f;
    for (int i = tid; i < 4 * 32; i += 96) z1[i] = 0.f;
    if (tid < 4) { xs[tid] = 0.f; xs[100 + tid] = 0.f; }

    const float* xrow = g_xt + ((size_t)b * CCH + c) * TLEN;
    if (tid < 96) xs[4 + tid] = xrow[tid];
    if (tid < 56) sw_h[tid] = w_hs[tid];
    if (tid < 24) sw_l[tid] = w_ls[tid];
    if (tid < 8) { sb_h[tid] = b_hs[tid]; sb_l[tid] = b_ls[tid]; }
    for (int i = tid; i < 224; i += 96) swi1_h[i] = w_hi1[c * 224 + i];
    for (int i = tid; i < 112; i += 96) swi2_h[i] = w_hi2[c * 112 + i];
    if (tid < 96)                       swi1_l[tid] = w_li1[c * 96 + tid];
    if (tid < 48)                       swi2_l[tid] = w_li2[c * 48 + tid];
    if (tid < 4) {
        sbi1_h[tid] = b_hi1[c * 4 + tid];
        sbi2_h[tid] = b_hi2[c * 4 + tid];
        sbi1_l[tid] = b_li1[c * 4 + tid];
        sbi2_l[tid] = b_li2[c * 4 + tid];
    }
    __syncthreads();

    float* fo = g_feat + (size_t)b * FIN + c * 108;
    const float* xsp = xs + 4;

    if (tid < 12) {   // slot 0: mean of 8
        float s = 0.f;
        #pragma unroll
        for (int k = 0; k < 8; k++) s += xsp[tid * 8 + k];
        fo[tid] = s * 0.125f;
    }

    run_branch<3, 1>(xsp, hs, z1, sw_l, sb_l, swi1_l, sbi1_l, swi2_l, sbi2_l, fo, 1, tid);
    run_branch<7, 3>(xsp, hs, z1, sw_h, sb_h, swi1_h, sbi1_h, swi2_h, sbi2_h, fo, 5, tid);
}

// ---------------------------------------------------------------------------
// Split-precision conversions
// ---------------------------------------------------------------------------
__device__ __forceinline__ void split8(const float* v, __nv_bfloat16* hi, __nv_bfloat16* lo) {
    #pragma unroll
    for (int i = 0; i < 8; i++) {
        __nv_bfloat16 h = __float2bfloat16(v[i]);
        hi[i] = h;
        lo[i] = __float2bfloat16(v[i] - __bfloat162float(h));
    }
}

__global__ void __launch_bounds__(256) convA_kernel(int m0) {
    const size_t idx = (size_t)blockIdx.x * 256 + threadIdx.x;   // HB*896
    const int m  = m0 + (int)(idx / 896);
    const int kb = (int)(idx % 896);
    const int k0 = kb * 8;
    float v[8];
    if (kb < 891) {
        float4 a = *(const float4*)(g_feat + (size_t)m * FIN + k0);
        float4 b = *(const float4*)(g_feat + (size_t)m * FIN + k0 + 4);
        v[0]=a.x; v[1]=a.y; v[2]=a.z; v[3]=a.w; v[4]=b.x; v[5]=b.y; v[6]=b.z; v[7]=b.w;
    } else {
        #pragma unroll
        for (int i = 0; i < 8; i++) v[i] = 0.f;
    }
    __align__(16) __nv_bfloat16 hi[8], lo[8];
    split8(v, hi, lo);
    __nv_bfloat16* dst = g_A2 + (size_t)m * KP + k0;
    *(uint4*)(dst)            = *(uint4*)hi;
    *(uint4*)(dst + KSEC)     = *(uint4*)hi;
    *(uint4*)(dst + 2 * KSEC) = *(uint4*)lo;
}

__global__ void __launch_bounds__(256) convB_kernel(const float* __restrict__ w1) {
    const size_t idx = (size_t)blockIdx.x * 256 + threadIdx.x;   // 2048*896
    const int n  = (int)(idx / 896);
    const int kb = (int)(idx % 896);
    const int k0 = kb * 8;
    float v[8];
    if (n < HID && kb < 891) {
        float4 a = *(const float4*)(w1 + (size_t)n * FIN + k0);
        float4 b = *(const float4*)(w1 + (size_t)n * FIN + k0 + 4);
        v[0]=a.x; v[1]=a.y; v[2]=a.z; v[3]=a.w; v[4]=b.x; v[5]=b.y; v[6]=b.z; v[7]=b.w;
    } else {
        #pragma unroll
        for (int i = 0; i < 8; i++) v[i] = 0.f;
    }
    __align__(16) __nv_bfloat16 hi[8], lo[8];
    split8(v, hi, lo);
    __nv_bfloat16* dst = g_B2 + (size_t)n * KP + k0;
    *(uint4*)(dst)            = *(uint4*)hi;
    *(uint4*)(dst + KSEC)     = *(uint4*)lo;
    *(uint4*)(dst + 2 * KSEC) = *(uint4*)hi;
}

// ---------------------------------------------------------------------------
// fc1 GEMM (HMMA bf16) — R4-exact kernel, M-offset for half launches.
// ---------------------------------------------------------------------------
constexpr int GSTAGES = 4;
constexpr int STAGE_BYTES = 16384;
constexpr int GSMEM_BYTES = GSTAGES * STAGE_BYTES;   // 64 KB

__global__ void __launch_bounds__(256) gemm_kernel(const float* __restrict__ bias,
                                                   int bm0) {
    extern __shared__ char smem[];
    const uint32_t smem_u32 = smem_to_u32(smem);
    const int tid  = threadIdx.x;
    const int wid  = tid >> 5;
    const int lane = tid & 31;
    const int bm = bm0 + blockIdx.y * 128;
    const int bn = blockIdx.x * 128;

    const int warp_m = wid & 1;
    const int warp_n = wid >> 1;

    const int lcu  = tid & 3;
    const int lrow = tid >> 2;
    const __nv_bfloat16* srcA[2];
    const __nv_bfloat16* srcB[2];
    uint32_t dstA[2], dstB[2];
    #pragma unroll
    for (int i = 0; i < 2; i++) {
        const int r = lrow + 64 * i;
        srcA[i] = g_A2 + (size_t)(bm + r) * KP + lcu * 8;
        srcB[i] = g_B2 + (size_t)(bn + r) * KP + lcu * 8;
        const uint32_t sw = (uint32_t)((lcu ^ ((r >> 1) & 3)) << 4);
        dstA[i] = r * 64 + sw;
        dstB[i] = 8192 + r * 64 + sw;
    }

    const int g8 = lane >> 3;
    const int l8 = lane & 7;
    uint32_t aoff[8];
    #pragma unroll
    for (int mt = 0; mt < 4; mt++) {
        const int mrow = warp_m * 64 + mt * 16 + (g8 & 1) * 8 + l8;
        const int s = (mrow >> 1) & 3;
        #pragma unroll
        for (int ks = 0; ks < 2; ks++) {
            const int cu = 2 * ks + (g8 >> 1);
            aoff[mt * 2 + ks] = mrow * 64 + ((cu ^ s) << 4);
        }
    }
    uint32_t boff[4];
    #pragma unroll
    for (int p = 0; p < 2; p++) {
        const int nrow = warp_n * 32 + p * 16 + (g8 >> 1) * 8 + l8;
        const int s = (nrow >> 1) & 3;
        #pragma unroll
        for (int ks = 0; ks < 2; ks++) {
            const int cu = 2 * ks + (g8 & 1);
            boff[p * 2 + ks] = 8192 + nrow * 64 + ((cu ^ s) << 4);
        }
    }

    float acc[4][4][4];
    #pragma unroll
    for (int mt = 0; mt < 4; mt++)
        #pragma unroll
        for (int nt = 0; nt < 4; nt++)
            #pragma unroll
            for (int e = 0; e < 4; e++) acc[mt][nt][e] = 0.f;

    #pragma unroll
    for (int kt = 0; kt < GSTAGES - 1; kt++) {
        const uint32_t sb = smem_u32 + kt * STAGE_BYTES;
        #pragma unroll
        for (int i = 0; i < 2; i++) {
            cp16(sb + dstA[i], srcA[i] + (size_t)kt * 32);
            cp16(sb + dstB[i], srcB[i] + (size_t)kt * 32);
        }
        CP_COMMIT();
    }

    for (int kt = 0; kt < KT; kt++) {
        CP_WAIT2();
        __syncthreads();

        const int knext = kt + GSTAGES - 1;
        if (knext < KT) {
            const uint32_t sb = smem_u32 + (knext & 3) * STAGE_BYTES;
            #pragma unroll
            for (int i = 0; i < 2; i++) {
                cp16(sb + dstA[i], srcA[i] + (size_t)knext * 32);
                cp16(sb + dstB[i], srcB[i] + (size_t)knext * 32);
            }
        }
        CP_COMMIT();

        const uint32_t sb = smem_u32 + (kt & 3) * STAGE_BYTES;
        #pragma unroll
        for (int ks = 0; ks < 2; ks++) {
            uint32_t afr[4][4], bfr[2][4];
            #pragma unroll
            for (int mt = 0; mt < 4; mt++) ldsm_x4(afr[mt], sb + aoff[mt * 2 + ks]);
            #pragma unroll
            for (int p = 0; p < 2; p++)    ldsm_x4(bfr[p],  sb + boff[p * 2 + ks]);
            #pragma unroll
            for (int mt = 0; mt < 4; mt++)
                #pragma unroll
                for (int nt = 0; nt < 4; nt++)
                    mma16816(acc[mt][nt], afr[mt],
                             bfr[nt >> 1][(nt & 1) * 2],
                             bfr[nt >> 1][(nt & 1) * 2 + 1]);
        }
    }

    const int qrow = lane >> 2;
    const int qcol = (lane & 3) * 2;
    #pragma unroll
    for (int mt = 0; mt < 4; mt++) {
        #pragma unroll
        for (int nt = 0; nt < 4; nt++) {
            const int n = bn + warp_n * 32 + nt * 8 + qcol;
            if (n >= HID) continue;
            const float b0 = bias[n], b1 = bias[n + 1];
            #pragma unroll
            for (int half = 0; half < 2; half++) {
                const int m = bm + warp_m * 64 + mt * 16 + qrow + half * 8;
                float* o = g_h + (size_t)m * HID + n;
                o[0] = fmaxf(acc[mt][nt][half * 2 + 0] + b0, 0.f);
                o[1] = fmaxf(acc[mt][nt][half * 2 + 1] + b1, 0.f);
            }
        }
    }
}

// ---------------------------------------------------------------------------
// fc2: warp-per-row, 14 outputs in registers; batch range [m0, m0+HB)
// ---------------------------------------------------------------------------
__global__ void __launch_bounds__(256) fc2_kernel(
    const float* __restrict__ w2, const float* __restrict__ b2,
    float* __restrict__ out, int m0)
{
    const int wid  = threadIdx.x >> 5;
    const int lane = threadIdx.x & 31;
    const int m = m0 + blockIdx.x * 8 + wid;

    const float* hrow = g_h + (size_t)m * HID;
    float acc[NCLS];
    #pragma unroll
    for (int n = 0; n < NCLS; n++) acc[n] = 0.f;

    for (int k = lane; k < HID; k += 32) {
        const float h = hrow[k];
        #pragma unroll
        for (int n = 0; n < NCLS; n++)
            acc[n] = fmaf(h, w2[n * HID + k], acc[n]);
    }
    #pragma unroll
    for (int n = 0; n < NCLS; n++)
        #pragma unroll
        for (int off = 16; off > 0; off >>= 1)
            acc[n] += __shfl_down_sync(0xffffffffu, acc[n], off);
    if (lane == 0) {
        #pragma unroll
        for (int n = 0; n < NCLS; n++)
            out[m * NCLS + n] = acc[n] + b2[n];
    }
}

// ---------------------------------------------------------------------------
// Entry — pipelined fork/join (graph-capturable):
//   s1: trans(h0) -> feat(h0) -> convA(h0) -> e1
//   s2: convB -> eB ; trans(h1) ; wait(e1) -> feat(h1) -> convA(h1) -> e2
//   s0: wait(e1,eB) -> gemm(h0) -> eG0 ; wait(e2) -> gemm(h1) -> fc2(h1)
//   s2: wait(eG0) -> fc2(h0)  (overlaps gemm(h1))
// ---------------------------------------------------------------------------
extern "C" void kernel_launch(void* const* d_in, const int* in_sizes, int n_in,
                              void* d_out, int out_size)
{
    const float* x     = (const float*)d_in[0];
    const float* w_hs  = (const float*)d_in[1];
    const float* b_hs  = (const float*)d_in[2];
    const float* w_ls  = (const float*)d_in[3];
    const float* b_ls  = (const float*)d_in[4];
    const float* w_hi1 = (const float*)d_in[5];
    const float* b_hi1 = (const float*)d_in[6];
    const float* w_hi2 = (const float*)d_in[7];
    const float* b_hi2 = (const float*)d_in[8];
    const float* w_li1 = (const float*)d_in[9];
    const float* b_li1 = (const float*)d_in[10];
    const float* w_li2 = (const float*)d_in[11];
    const float* b_li2 = (const float*)d_in[12];
    const float* w_fc1 = (const float*)d_in[13];
    const float* b_fc1 = (const float*)d_in[14];
    const float* w_fc2 = (const float*)d_in[15];
    const float* b_fc2 = (const float*)d_in[16];
    float* out = (float*)d_out;

    static cudaStream_t s1 = nullptr, s2 = nullptr;
    static cudaEvent_t eRoot, e1, e2, eB, eG0, eF0;
    if (!s1) {
        cudaStreamCreateWithFlags(&s1, cudaStreamNonBlocking);
        cudaStreamCreateWithFlags(&s2, cudaStreamNonBlocking);
        cudaEventCreateWithFlags(&eRoot, cudaEventDisableTiming);
        cudaEventCreateWithFlags(&e1,    cudaEventDisableTiming);
        cudaEventCreateWithFlags(&e2,    cudaEventDisableTiming);
        cudaEventCreateWithFlags(&eB,    cudaEventDisableTiming);
        cudaEventCreateWithFlags(&eG0,   cudaEventDisableTiming);
        cudaEventCreateWithFlags(&eF0,   cudaEventDisableTiming);
        cudaFuncSetAttribute(gemm_kernel, cudaFuncAttributeMaxDynamicSharedMemorySize,
                             GSMEM_BYTES);
    }

    // fork from the (captured) default stream
    cudaEventRecord(eRoot, 0);
    cudaStreamWaitEvent(s1, eRoot, 0);
    cudaStreamWaitEvent(s2, eRoot, 0);

    // s1: half-0 feature chain (gets nearly the whole chip)
    transpose_kernel<<<HB, 256, 0, s1>>>(x, 0);
    feat_kernel<<<dim3(CCH, HB), 96, 0, s1>>>(w_hs, b_hs, w_ls, b_ls,
                                              w_hi1, b_hi1, w_hi2, b_hi2,
                                              w_li1, b_li1, w_li2, b_li2, 0);
    convA_kernel<<<(HB * 896) / 256, 256, 0, s1>>>(0);
    cudaEventRecord(e1, s1);

    // s2: small independent work first; feat(h1) only AFTER h0 chain done
    convB_kernel<<<(NPAD * 896) / 256, 256, 0, s2>>>(w_fc1);
    cudaEventRecord(eB, s2);
    transpose_kernel<<<HB, 256, 0, s2>>>(x, HB);
    cudaStreamWaitEvent(s2, e1, 0);                       // serialize feat halves
    feat_kernel<<<dim3(CCH, HB), 96, 0, s2>>>(w_hs, b_hs, w_ls, b_ls,
                                              w_hi1, b_hi1, w_hi2, b_hi2,
                                              w_li1, b_li1, w_li2, b_li2, HB);
    convA_kernel<<<(HB * 896) / 256, 256, 0, s2>>>(HB);
    cudaEventRecord(e2, s2);

    // default: gemm(h0) co-runs with feat(h1); then gemm(h1) + fc2(h1)
    cudaStreamWaitEvent(0, e1, 0);
    cudaStreamWaitEvent(0, eB, 0);
    gemm_kernel<<<dim3(16, 8), 256, GSMEM_BYTES>>>(b_fc1, 0);
    cudaEventRecord(eG0, 0);
    cudaStreamWaitEvent(0, e2, 0);
    gemm_kernel<<<dim3(16, 8), 256, GSMEM_BYTES>>>(b_fc1, HB);

    // s2: fc2(h0) overlaps gemm(h1)
    cudaStreamWaitEvent(s2, eG0, 0);
    fc2_kernel<<<HB / 8, 256, 0, s2>>>(w_fc2, b_fc2, out, 0);
    cudaEventRecord(eF0, s2);

    fc2_kernel<<<HB / 8, 256>>>(w_fc2, b_fc2, out, HB);
    cudaStreamWaitEvent(0, eF0, 0);   // join so the default stream ends last
}